// round 9
// baseline (speedup 1.0000x reference)
#include <cuda_runtime.h>
#include <math.h>
#include <stdint.h>

// Problem constants
#define NSPH 7
#define NRAD 6
#define ROW  48          // padded rbf row (42 used), 192 bytes
#define CAP_E 1048576    // capacity for edges (E = 1,000,000)

// Scratch: per-edge rbf (env * norm * j_l), padded rows (~201 MB static).
__device__ float g_rbf[(size_t)CAP_E * ROW];
// idx dtype flag: 1 => int64 input, 0 => int32 input
__device__ int g_idx_is64;

// sqrt((2l+1)/(4*pi)) in double, rounded to f32 (matches numpy cast)
__device__ __constant__ float c_coef[NSPH] = {
    (float)0.28209479177387814,
    (float)0.48860251190291992,
    (float)0.63078313050504009,
    (float)0.74635266518023078,
    (float)0.84628437532163443,
    (float)0.93560257962738882,
    (float)1.01710723628205748
};

// ===========================================================================
// glibc scalar sinf/cosf port (sysdeps/ieee754/flt-32/s_sincosf, glibc>=2.28).
// Double-internal, TOINT_INTRINSICS reduction path (aarch64), gcc
// -ffp-contract=fast fma placement. Valid for |x| < 120 (args here < 30).
// ===========================================================================
#define GSC_HPI_INV 0x1.45F306DC9C883p-1   /* 2/pi */
#define GSC_HPI     0x1.921FB54442D18p0    /* pi/2 */
// cosine polynomial
#define GSC_C0  (1.0)
#define GSC_C1  (-0x1.ffffffd0c621cp-2)
#define GSC_C2  ( 0x1.55553e1068f19p-5)
#define GSC_C3  (-0x1.6c087e89a359dp-10)
#define GSC_C4  ( 0x1.99343027bf8c3p-16)
// sine polynomial
#define GSC_S1  (-0x1.555545995a603p-3)
#define GSC_S2  ( 0x1.1107605230bc4p-7)
#define GSC_S3  (-0x1.994eb3774cf24p-13)

__device__ __forceinline__ unsigned gsc_abstop12(float y) {
    return (__float_as_uint(y) >> 20) & 0x7ffu;
}
// sign[k] = {1,-1,-1,1}[k&3]
__device__ __forceinline__ double gsc_sign(int k) {
    return ((k + 1) & 2) ? -1.0 : 1.0;
}

// sinf_poly: n even -> sine poly, n odd -> cosine poly (negcos flips cos coeffs)
__device__ __forceinline__ float gsc_sinf_poly(double x, double x2, int negcos, int n)
{
    if ((n & 1) == 0) {
        double x3 = x * x2;
        double s1 = fma(x2, GSC_S3, GSC_S2);
        double x7 = x3 * x2;
        double s  = fma(x3, GSC_S1, x);
        return (float)fma(x7, s1, s);
    } else {
        double c0 = negcos ? -GSC_C0 : GSC_C0;
        double k1 = negcos ? -GSC_C1 : GSC_C1;
        double k2 = negcos ? -GSC_C2 : GSC_C2;
        double k3 = negcos ? -GSC_C3 : GSC_C3;
        double k4 = negcos ? -GSC_C4 : GSC_C4;
        double x4 = x2 * x2;
        double c2 = fma(x2, k4, k3);
        double c1 = fma(x2, k1, c0);
        double x6 = x4 * x2;
        double c  = fma(x4, k2, c1);
        return (float)fma(x6, c2, c);
    }
}

__device__ __forceinline__ float gsc_sinf(float y) {
    double x = (double)y;
    unsigned at = gsc_abstop12(y);
    if (at < 0x3f4u) {                       // |y| < ~pi/4
        if (at < 0x398u) return y;           // |y| < 0x1p-12
        return gsc_sinf_poly(x, x * x, 0, 0);
    }
    // reduce: n = rint(x * 2/pi); x -= n * pi/2 (fused)
    double r  = x * GSC_HPI_INV;
    double rd = rint(r);
    int    n  = (int)rd;
    x = fma(-rd, GSC_HPI, x);
    double s = gsc_sign(n & 3);
    int negcos = (n & 2) ? 1 : 0;
    return gsc_sinf_poly(x * s, x * x, negcos, n);
}

__device__ __forceinline__ float gsc_cosf(float y) {
    double x = (double)y;
    unsigned at = gsc_abstop12(y);
    if (at < 0x3f4u) {
        if (at < 0x398u) return 1.0f;
        return gsc_sinf_poly(x, x * x, 0, 1);
    }
    double r  = x * GSC_HPI_INV;
    double rd = rint(r);
    int    n  = (int)rd;
    x = fma(-rd, GSC_HPI, x);
    double s = gsc_sign((n + 1) & 3);
    int negcos = ((n + 1) & 2) ? 1 : 0;
    return gsc_sinf_poly(x * s, x * x, negcos, n ^ 1);
}

// ---------------------------------------------------------------------------
// Probe: int64 vs int32 idx_kj (odd 32-bit words all zero <=> int64 LE).
// ---------------------------------------------------------------------------
__global__ void probe_idx_kernel(const int* __restrict__ idx32, int n_check) {
    __shared__ int any_nz;
    if (threadIdx.x == 0) any_nz = 0;
    __syncthreads();
    for (int i = threadIdx.x; i < n_check; i += blockDim.x) {
        if (idx32[2 * i + 1] != 0) any_nz = 1;
    }
    __syncthreads();
    if (threadIdx.x == 0) g_idx_is64 = (any_nz == 0) ? 1 : 0;
}

// ---------------------------------------------------------------------------
// K1: per-edge rbf. XLA:CPU (Grace, scalar glibc libm) semantics:
//  - x = dist * 0.2f (algebraic simplifier reciprocal rewrite, CONFIRMED)
//  - glibc scalar sinf/cosf (exact port above)
//  - IEEE div.rn for non-constant-denominator divisions
//  - NO FMA contraction in user-level fp32 arithmetic
// ---------------------------------------------------------------------------
__global__ void rbf_kernel(const float* __restrict__ dist,
                           const float* __restrict__ zeros_lk,
                           const float* __restrict__ norm_lk,
                           int E)
{
    __shared__ float s_z[NSPH * NRAD];
    __shared__ float s_n[NSPH * NRAD];
    if (threadIdx.x < NSPH * NRAD) {
        s_z[threadIdx.x] = zeros_lk[threadIdx.x];
        s_n[threadIdx.x] = norm_lk[threadIdx.x];
    }
    __syncthreads();

    int e = blockIdx.x * blockDim.x + threadIdx.x;
    if (e >= E) return;

    float d = dist[e];
    float x = __fmul_rn(d, 0.2f);            // x = dist * (1/CUTOFF)

    // x^5 via square-and-multiply (matches lax.integer_pow(x, 5))
    float x2  = __fmul_rn(x, x);
    float x4  = __fmul_rn(x2, x2);
    float xp0 = __fmul_rn(x4, x);

    // env = 1/x + a*x^5 + (b*x^5)*x + ((c*x^5)*x)*x   (strict, no fma)
    float t1 = __fdiv_rn(1.0f, x);
    float t2 = __fmul_rn(-28.0f, xp0);
    float t3 = __fmul_rn(__fmul_rn(48.0f, xp0), x);
    float t4 = __fmul_rn(__fmul_rn(__fmul_rn(-21.0f, xp0), x), x);
    float env = __fadd_rn(__fadd_rn(__fadd_rn(t1, t2), t3), t4);

    float* row = g_rbf + (size_t)e * ROW;

    #pragma unroll 1
    for (int l = 0; l < NSPH; ++l) {
        float v[NRAD];
        #pragma unroll 1
        for (int r = 0; r < NRAD; ++r) {
            float arg = __fmul_rn(x, s_z[l * NRAD + r]);
            float s = gsc_sinf(arg);
            float j = __fdiv_rn(s, arg);                  // j0
            if (l > 0) {
                float c = gsc_cosf(arg);
                // j1 = s/(arg*arg) - c/arg  (strict)
                float jc = __fsub_rn(__fdiv_rn(s, __fmul_rn(arg, arg)),
                                     __fdiv_rn(c, arg));
                float jm = j;
                for (int i = 2; i <= l; ++i) {
                    // ((2i-1)/arg)*jc - jm  (strict: div, mul, sub)
                    float coef = __fdiv_rn((float)(2 * i - 1), arg);
                    float jn = __fsub_rn(__fmul_rn(coef, jc), jm);
                    jm = jc; jc = jn;
                }
                j = jc;
            }
            v[r] = __fmul_rn(env, __fmul_rn(s_n[l * NRAD + r], j));
        }
        float2* dst = reinterpret_cast<float2*>(row + l * NRAD);
        dst[0] = make_float2(v[0], v[1]);
        dst[1] = make_float2(v[2], v[3]);
        dst[2] = make_float2(v[4], v[5]);
    }
}

// ---------------------------------------------------------------------------
// K2: per-triplet gather + Legendre * coef + store.
// ---------------------------------------------------------------------------
__global__ void out_kernel(const float* __restrict__ angle,
                           const int* __restrict__ idx32,
                           float* __restrict__ out,
                           int T)
{
    int t = blockIdx.x * blockDim.x + threadIdx.x;
    if (t >= T) return;

    int e = g_idx_is64 ? idx32[2 * t] : idx32[t];

    float ct = gsc_cosf(angle[t]);
    float P0 = 1.0f;
    float P1 = ct;
    // P_l = ((2l-1)*ct*P_{l-1} - (l-1)*P_{l-2}) * (1/l)   (strict)
    float P2 = __fmul_rn(__fsub_rn(__fmul_rn(__fmul_rn(3.0f,  ct), P1), P0),                   0.5f);
    float P3 = __fmul_rn(__fsub_rn(__fmul_rn(__fmul_rn(5.0f,  ct), P2), __fmul_rn(2.0f, P1)), 0.33333334f);
    float P4 = __fmul_rn(__fsub_rn(__fmul_rn(__fmul_rn(7.0f,  ct), P3), __fmul_rn(3.0f, P2)), 0.25f);
    float P5 = __fmul_rn(__fsub_rn(__fmul_rn(__fmul_rn(9.0f,  ct), P4), __fmul_rn(4.0f, P3)), 0.2f);
    float P6 = __fmul_rn(__fsub_rn(__fmul_rn(__fmul_rn(11.0f, ct), P5), __fmul_rn(5.0f, P4)), 0.16666667f);

    float cbf[NSPH];
    cbf[0] = __fmul_rn(P0, c_coef[0]);
    cbf[1] = __fmul_rn(P1, c_coef[1]);
    cbf[2] = __fmul_rn(P2, c_coef[2]);
    cbf[3] = __fmul_rn(P3, c_coef[3]);
    cbf[4] = __fmul_rn(P4, c_coef[4]);
    cbf[5] = __fmul_rn(P5, c_coef[5]);
    cbf[6] = __fmul_rn(P6, c_coef[6]);

    // gather 42 floats (11 x float4 covers indices 0..43; 42,43 pad)
    const float4* src = reinterpret_cast<const float4*>(g_rbf + (size_t)e * ROW);
    float rb[44];
    #pragma unroll
    for (int q = 0; q < 11; ++q) {
        float4 f = src[q];
        rb[4 * q + 0] = f.x;
        rb[4 * q + 1] = f.y;
        rb[4 * q + 2] = f.z;
        rb[4 * q + 3] = f.w;
    }

    float2* o = reinterpret_cast<float2*>(out + (size_t)t * 42);
    #pragma unroll
    for (int q = 0; q < 21; ++q) {
        const int k0 = 2 * q;
        const int k1 = 2 * q + 1;
        o[q] = make_float2(__fmul_rn(rb[k0], cbf[k0 / 6]),
                           __fmul_rn(rb[k1], cbf[k1 / 6]));
    }
}

// ---------------------------------------------------------------------------
// Launch
// ---------------------------------------------------------------------------
extern "C" void kernel_launch(void* const* d_in, const int* in_sizes, int n_in,
                              void* d_out, int out_size)
{
    const float* dist     = (const float*)d_in[0];
    const float* angle    = (const float*)d_in[1];
    const int*   idx32    = (const int*)  d_in[2];   // int32 or int64 (probed)
    const float* zeros_lk = (const float*)d_in[3];
    const float* norm_lk  = (const float*)d_in[4];
    float* out = (float*)d_out;

    int E = in_sizes[0];
    int T = in_sizes[1];
    if (E > CAP_E) E = CAP_E;

    int n_check = 2048;
    if (2 * n_check > T) n_check = T / 2;
    probe_idx_kernel<<<1, 256>>>(idx32, n_check);

    {
        int threads = 128;
        int blocks = (E + threads - 1) / threads;
        rbf_kernel<<<blocks, threads>>>(dist, zeros_lk, norm_lk, E);
    }
    {
        int threads = 128;
        int blocks = (T + threads - 1) / threads;
        out_kernel<<<blocks, threads>>>(angle, idx32, out, T);
    }
}

// round 10
// speedup vs baseline: 3.0542x; 3.0542x over previous
#include <cuda_runtime.h>
#include <math.h>
#include <stdint.h>

// Problem constants
#define NSPH 7
#define NRAD 6
#define ROW  48          // padded rbf row (42 used), 192 bytes
#define CAP_E 1048576    // capacity for edges (E = 1,000,000)

// Scratch (static device arrays; no allocation)
__device__ float g_rbf[(size_t)CAP_E * ROW];
__device__ int   g_perm[CAP_E];
__device__ unsigned g_hist[256];
__device__ unsigned g_off[256];
__device__ int   g_idx_is64;

// sqrt((2l+1)/(4*pi)) in double, rounded to f32 (matches numpy cast)
__device__ __constant__ float c_coef[NSPH] = {
    (float)0.28209479177387814,
    (float)0.48860251190291992,
    (float)0.63078313050504009,
    (float)0.74635266518023078,
    (float)0.84628437532163443,
    (float)0.93560257962738882,
    (float)1.01710723628205748
};

// exact-path thresholds per l: below this arg, use bit-exact glibc-DP path
__device__ __constant__ float c_th[NSPH] = {0.5f, 0.5f, 4.0f, 5.0f, 6.0f, 7.0f, 8.0f};

// ===========================================================================
// glibc scalar sinf/cosf port (sysdeps/ieee754/flt-32/s_sincosf).
// Confirmed bit-exact vs reference (round 9, rel_err == 0.0).
// ===========================================================================
#define GSC_HPI_INV 0x1.45F306DC9C883p-1   /* 2/pi */
#define GSC_HPI     0x1.921FB54442D18p0    /* pi/2 */
#define GSC_C0  (1.0)
#define GSC_C1  (-0x1.ffffffd0c621cp-2)
#define GSC_C2  ( 0x1.55553e1068f19p-5)
#define GSC_C3  (-0x1.6c087e89a359dp-10)
#define GSC_C4  ( 0x1.99343027bf8c3p-16)
#define GSC_S1  (-0x1.555545995a603p-3)
#define GSC_S2  ( 0x1.1107605230bc4p-7)
#define GSC_S3  (-0x1.994eb3774cf24p-13)

__device__ __forceinline__ unsigned gsc_abstop12(float y) {
    return (__float_as_uint(y) >> 20) & 0x7ffu;
}
__device__ __forceinline__ double gsc_sign(int k) {
    return ((k + 1) & 2) ? -1.0 : 1.0;
}
__device__ __forceinline__ float gsc_sinf_poly(double x, double x2, int negcos, int n)
{
    if ((n & 1) == 0) {
        double x3 = x * x2;
        double s1 = fma(x2, GSC_S3, GSC_S2);
        double x7 = x3 * x2;
        double s  = fma(x3, GSC_S1, x);
        return (float)fma(x7, s1, s);
    } else {
        double c0 = negcos ? -GSC_C0 : GSC_C0;
        double k1 = negcos ? -GSC_C1 : GSC_C1;
        double k2 = negcos ? -GSC_C2 : GSC_C2;
        double k3 = negcos ? -GSC_C3 : GSC_C3;
        double k4 = negcos ? -GSC_C4 : GSC_C4;
        double x4 = x2 * x2;
        double c2 = fma(x2, k4, k3);
        double c1 = fma(x2, k1, c0);
        double x6 = x4 * x2;
        double c  = fma(x4, k2, c1);
        return (float)fma(x6, c2, c);
    }
}
__device__ __forceinline__ float gsc_sinf(float y) {
    double x = (double)y;
    unsigned at = gsc_abstop12(y);
    if (at < 0x3f4u) {
        if (at < 0x398u) return y;
        return gsc_sinf_poly(x, x * x, 0, 0);
    }
    double r  = x * GSC_HPI_INV;
    double rd = rint(r);
    int    n  = (int)rd;
    x = fma(-rd, GSC_HPI, x);
    double s = gsc_sign(n & 3);
    int negcos = (n & 2) ? 1 : 0;
    return gsc_sinf_poly(x * s, x * x, negcos, n);
}
// fused sin+cos: bit-identical to calling gsc_sinf and gsc_cosf separately
__device__ __forceinline__ void gsc_sincosf(float y, float* sp, float* cp) {
    double x = (double)y;
    unsigned at = gsc_abstop12(y);
    if (at < 0x3f4u) {
        if (at < 0x398u) { *sp = y; *cp = 1.0f; return; }
        double x2 = x * x;
        *sp = gsc_sinf_poly(x, x2, 0, 0);
        *cp = gsc_sinf_poly(x, x2, 0, 1);
        return;
    }
    double r  = x * GSC_HPI_INV;
    double rd = rint(r);
    int    n  = (int)rd;
    x = fma(-rd, GSC_HPI, x);
    double x2 = x * x;
    {
        double s = gsc_sign(n & 3);
        int negcos = (n & 2) ? 1 : 0;
        *sp = gsc_sinf_poly(x * s, x2, negcos, n);
    }
    {
        int n1 = n + 1;
        double s = gsc_sign(n1 & 3);
        int negcos = (n1 & 2) ? 1 : 0;
        *cp = gsc_sinf_poly(x * s, x2, negcos, n ^ 1);
    }
}

// ---------------------------------------------------------------------------
// Probe: int64 vs int32 idx_kj
// ---------------------------------------------------------------------------
__global__ void probe_idx_kernel(const int* __restrict__ idx32, int n_check) {
    __shared__ int any_nz;
    if (threadIdx.x == 0) any_nz = 0;
    __syncthreads();
    for (int i = threadIdx.x; i < n_check; i += blockDim.x) {
        if (idx32[2 * i + 1] != 0) any_nz = 1;
    }
    __syncthreads();
    if (threadIdx.x == 0) g_idx_is64 = (any_nz == 0) ? 1 : 0;
}

// ---------------------------------------------------------------------------
// Counting sort of edges by dist (256 bins) -> g_perm, for warp-coherent
// precision branching in rbf_kernel.
// ---------------------------------------------------------------------------
__global__ void zero_hist_kernel() {
    int t = threadIdx.x;
    if (t < 256) g_hist[t] = 0u;
}
__device__ __forceinline__ int dist_bin(float d) {
    int b = (int)((d - 0.1f) * (256.0f / 4.9f));
    return min(255, max(0, b));
}
__global__ void hist_kernel(const float* __restrict__ dist, int E) {
    int i = blockIdx.x * blockDim.x + threadIdx.x;
    if (i >= E) return;
    atomicAdd(&g_hist[dist_bin(dist[i])], 1u);
}
__global__ void scan_kernel() {
    __shared__ unsigned tmp[256];
    int t = threadIdx.x;
    unsigned own = g_hist[t];
    tmp[t] = own;
    __syncthreads();
    for (int off = 1; off < 256; off <<= 1) {
        unsigned v = tmp[t];
        __syncthreads();
        if (t >= off) v += tmp[t - off];
        __syncthreads();
        tmp[t] = v;
        __syncthreads();
    }
    g_off[t] = tmp[t] - own;   // exclusive prefix
}
__global__ void scatter_kernel(const float* __restrict__ dist, int E) {
    int i = blockIdx.x * blockDim.x + threadIdx.x;
    if (i >= E) return;
    unsigned pos = atomicAdd(&g_off[dist_bin(dist[i])], 1u);
    g_perm[pos] = i;
}

// ---------------------------------------------------------------------------
// K1: per-edge rbf. Hybrid precision:
//  - arg <  TH(l): bit-exact reference pipeline (glibc-DP sincos, strict
//    div.rn/mul/sub order) -- required where recurrence amplifies ulp noise
//  - arg >= TH(l): fp32 libdevice sincosf + reciprocal-multiply recurrence
//    (deviation < ~1e-5 per entry; amplification bounded in this regime)
// Edges processed in dist-sorted order (g_perm) so the branch is
// warp-coherent.
// ---------------------------------------------------------------------------
__global__ void __launch_bounds__(256) rbf_kernel(
    const float* __restrict__ dist,
    const float* __restrict__ zeros_lk,
    const float* __restrict__ norm_lk,
    int E)
{
    __shared__ float s_z[NSPH * NRAD];
    __shared__ float s_n[NSPH * NRAD];
    if (threadIdx.x < NSPH * NRAD) {
        s_z[threadIdx.x] = zeros_lk[threadIdx.x];
        s_n[threadIdx.x] = norm_lk[threadIdx.x];
    }
    __syncthreads();

    int i = blockIdx.x * blockDim.x + threadIdx.x;
    if (i >= E) return;
    int e = g_perm[i];

    float d = dist[e];
    float x = __fmul_rn(d, 0.2f);            // x = dist * (1/CUTOFF)

    // x^5 square-and-multiply (matches lax.integer_pow)
    float x2  = __fmul_rn(x, x);
    float x4  = __fmul_rn(x2, x2);
    float xp0 = __fmul_rn(x4, x);

    // env (strict, no fma)
    float t1 = __fdiv_rn(1.0f, x);
    float t2 = __fmul_rn(-28.0f, xp0);
    float t3 = __fmul_rn(__fmul_rn(48.0f, xp0), x);
    float t4 = __fmul_rn(__fmul_rn(__fmul_rn(-21.0f, xp0), x), x);
    float env = __fadd_rn(__fadd_rn(__fadd_rn(t1, t2), t3), t4);

    float* row = g_rbf + (size_t)e * ROW;

    #pragma unroll 1
    for (int l = 0; l < NSPH; ++l) {
        float th = c_th[l];
        float v[NRAD];
        #pragma unroll 1
        for (int r = 0; r < NRAD; ++r) {
            float arg = __fmul_rn(x, s_z[l * NRAD + r]);
            float j;
            if (arg < th) {
                // ---- exact reference path (bit-identical to round 9) ----
                if (l == 0) {
                    float s = gsc_sinf(arg);
                    j = __fdiv_rn(s, arg);
                } else {
                    float s, c;
                    gsc_sincosf(arg, &s, &c);
                    float j0 = __fdiv_rn(s, arg);
                    float jc = __fsub_rn(__fdiv_rn(s, __fmul_rn(arg, arg)),
                                         __fdiv_rn(c, arg));
                    float jm = j0;
                    for (int ii = 2; ii <= l; ++ii) {
                        float coef = __fdiv_rn((float)(2 * ii - 1), arg);
                        float jn = __fsub_rn(__fmul_rn(coef, jc), jm);
                        jm = jc; jc = jn;
                    }
                    j = jc;
                }
            } else {
                // ---- fast fp32 path (stable regime) ----
                if (l == 0) {
                    float s = sinf(arg);                  // libdevice, ~1.5 ulp
                    j = s * __fdiv_rn(1.0f, arg);
                } else {
                    float s, c;
                    sincosf(arg, &s, &c);                 // libdevice accurate
                    float inv = __fdiv_rn(1.0f, arg);     // one div per cell
                    float j0 = s * inv;
                    float jc = (j0 - c) * inv;            // j1 = (s/z - c)/z
                    float jm = j0;
                    #pragma unroll
                    for (int ii = 2; ii <= 6; ++ii) {
                        if (ii > l) break;
                        float jn = fmaf((float)(2 * ii - 1) * inv, jc, -jm);
                        jm = jc; jc = jn;
                    }
                    j = jc;
                }
            }
            v[r] = __fmul_rn(env, __fmul_rn(s_n[l * NRAD + r], j));
        }
        float2* dst = reinterpret_cast<float2*>(row + l * NRAD);
        dst[0] = make_float2(v[0], v[1]);
        dst[1] = make_float2(v[2], v[3]);
        dst[2] = make_float2(v[4], v[5]);
    }
}

// ---------------------------------------------------------------------------
// K2: per-triplet gather + Legendre * coef + store.
// fp32 cosf is safe here: Legendre amplification ~O(30) -> ~3e-6 relative.
// ---------------------------------------------------------------------------
__global__ void __launch_bounds__(128) out_kernel(
    const float* __restrict__ angle,
    const int* __restrict__ idx32,
    float* __restrict__ out,
    int T)
{
    int t = blockIdx.x * blockDim.x + threadIdx.x;
    if (t >= T) return;

    int e = g_idx_is64 ? idx32[2 * t] : idx32[t];

    float ct = cosf(angle[t]);                 // libdevice, ~1.5 ulp
    float P0 = 1.0f;
    float P1 = ct;
    float P2 = __fmul_rn(__fsub_rn(__fmul_rn(__fmul_rn(3.0f,  ct), P1), P0),                   0.5f);
    float P3 = __fmul_rn(__fsub_rn(__fmul_rn(__fmul_rn(5.0f,  ct), P2), __fmul_rn(2.0f, P1)), 0.33333334f);
    float P4 = __fmul_rn(__fsub_rn(__fmul_rn(__fmul_rn(7.0f,  ct), P3), __fmul_rn(3.0f, P2)), 0.25f);
    float P5 = __fmul_rn(__fsub_rn(__fmul_rn(__fmul_rn(9.0f,  ct), P4), __fmul_rn(4.0f, P3)), 0.2f);
    float P6 = __fmul_rn(__fsub_rn(__fmul_rn(__fmul_rn(11.0f, ct), P5), __fmul_rn(5.0f, P4)), 0.16666667f);

    float cbf[NSPH];
    cbf[0] = __fmul_rn(P0, c_coef[0]);
    cbf[1] = __fmul_rn(P1, c_coef[1]);
    cbf[2] = __fmul_rn(P2, c_coef[2]);
    cbf[3] = __fmul_rn(P3, c_coef[3]);
    cbf[4] = __fmul_rn(P4, c_coef[4]);
    cbf[5] = __fmul_rn(P5, c_coef[5]);
    cbf[6] = __fmul_rn(P6, c_coef[6]);

    const float4* src = reinterpret_cast<const float4*>(g_rbf + (size_t)e * ROW);
    float rb[44];
    #pragma unroll
    for (int q = 0; q < 11; ++q) {
        float4 f = src[q];
        rb[4 * q + 0] = f.x;
        rb[4 * q + 1] = f.y;
        rb[4 * q + 2] = f.z;
        rb[4 * q + 3] = f.w;
    }

    float2* o = reinterpret_cast<float2*>(out + (size_t)t * 42);
    #pragma unroll
    for (int q = 0; q < 21; ++q) {
        const int k0 = 2 * q;
        const int k1 = 2 * q + 1;
        o[q] = make_float2(__fmul_rn(rb[k0], cbf[k0 / 6]),
                           __fmul_rn(rb[k1], cbf[k1 / 6]));
    }
}

// ---------------------------------------------------------------------------
// Launch
// ---------------------------------------------------------------------------
extern "C" void kernel_launch(void* const* d_in, const int* in_sizes, int n_in,
                              void* d_out, int out_size)
{
    const float* dist     = (const float*)d_in[0];
    const float* angle    = (const float*)d_in[1];
    const int*   idx32    = (const int*)  d_in[2];
    const float* zeros_lk = (const float*)d_in[3];
    const float* norm_lk  = (const float*)d_in[4];
    float* out = (float*)d_out;

    int E = in_sizes[0];
    int T = in_sizes[1];
    if (E > CAP_E) E = CAP_E;

    int n_check = 2048;
    if (2 * n_check > T) n_check = T / 2;
    probe_idx_kernel<<<1, 256>>>(idx32, n_check);

    // counting sort by dist
    zero_hist_kernel<<<1, 256>>>();
    hist_kernel<<<(E + 255) / 256, 256>>>(dist, E);
    scan_kernel<<<1, 256>>>();
    scatter_kernel<<<(E + 255) / 256, 256>>>(dist, E);

    rbf_kernel<<<(E + 255) / 256, 256>>>(dist, zeros_lk, norm_lk, E);
    out_kernel<<<(T + 127) / 128, 128>>>(angle, idx32, out, T);
}

// round 11
// speedup vs baseline: 3.8957x; 1.2755x over previous
#include <cuda_runtime.h>
#include <math.h>
#include <stdint.h>

// Problem constants
#define NSPH 7
#define NRAD 6
#define ROW  48          // padded rbf row (42 used), 192 bytes
#define CAP_E 1048576    // capacity for edges (E = 1,000,000)

// Scratch (static device arrays; no allocation)
__device__ float g_rbf[(size_t)CAP_E * ROW];
__device__ int   g_perm[CAP_E];
__device__ unsigned g_hist[256];
__device__ unsigned g_off[256];
__device__ int   g_idx_is64;

// sqrt((2l+1)/(4*pi)) in double, rounded to f32 (matches numpy cast)
__device__ __constant__ float c_coef[NSPH] = {
    (float)0.28209479177387814,
    (float)0.48860251190291992,
    (float)0.63078313050504009,
    (float)0.74635266518023078,
    (float)0.84628437532163443,
    (float)0.93560257962738882,
    (float)1.01710723628205748
};

// exact-path thresholds per l (below: bit-exact glibc-DP path)
__device__ __constant__ float c_th[NSPH] = {0.5f, 0.5f, 3.0f, 4.0f, 5.0f, 6.0f, 7.0f};

// ===========================================================================
// glibc scalar sinf/cosf port (sysdeps/ieee754/flt-32/s_sincosf).
// Confirmed bit-exact vs reference (round 9, rel_err == 0.0).
// ===========================================================================
#define GSC_HPI_INV 0x1.45F306DC9C883p-1   /* 2/pi */
#define GSC_HPI     0x1.921FB54442D18p0    /* pi/2 */
#define GSC_C0  (1.0)
#define GSC_C1  (-0x1.ffffffd0c621cp-2)
#define GSC_C2  ( 0x1.55553e1068f19p-5)
#define GSC_C3  (-0x1.6c087e89a359dp-10)
#define GSC_C4  ( 0x1.99343027bf8c3p-16)
#define GSC_S1  (-0x1.555545995a603p-3)
#define GSC_S2  ( 0x1.1107605230bc4p-7)
#define GSC_S3  (-0x1.994eb3774cf24p-13)

__device__ __forceinline__ unsigned gsc_abstop12(float y) {
    return (__float_as_uint(y) >> 20) & 0x7ffu;
}
__device__ __forceinline__ double gsc_sign(int k) {
    return ((k + 1) & 2) ? -1.0 : 1.0;
}
__device__ __forceinline__ float gsc_sinf_poly(double x, double x2, int negcos, int n)
{
    if ((n & 1) == 0) {
        double x3 = x * x2;
        double s1 = fma(x2, GSC_S3, GSC_S2);
        double x7 = x3 * x2;
        double s  = fma(x3, GSC_S1, x);
        return (float)fma(x7, s1, s);
    } else {
        double c0 = negcos ? -GSC_C0 : GSC_C0;
        double k1 = negcos ? -GSC_C1 : GSC_C1;
        double k2 = negcos ? -GSC_C2 : GSC_C2;
        double k3 = negcos ? -GSC_C3 : GSC_C3;
        double k4 = negcos ? -GSC_C4 : GSC_C4;
        double x4 = x2 * x2;
        double c2 = fma(x2, k4, k3);
        double c1 = fma(x2, k1, c0);
        double x6 = x4 * x2;
        double c  = fma(x4, k2, c1);
        return (float)fma(x6, c2, c);
    }
}
__device__ __forceinline__ float gsc_sinf(float y) {
    double x = (double)y;
    unsigned at = gsc_abstop12(y);
    if (at < 0x3f4u) {
        if (at < 0x398u) return y;
        return gsc_sinf_poly(x, x * x, 0, 0);
    }
    double r  = x * GSC_HPI_INV;
    double rd = rint(r);
    int    n  = (int)rd;
    x = fma(-rd, GSC_HPI, x);
    double s = gsc_sign(n & 3);
    int negcos = (n & 2) ? 1 : 0;
    return gsc_sinf_poly(x * s, x * x, negcos, n);
}
// fused sin+cos: bit-identical to calling scalar sinf and cosf separately
__device__ __forceinline__ void gsc_sincosf(float y, float* sp, float* cp) {
    double x = (double)y;
    unsigned at = gsc_abstop12(y);
    if (at < 0x3f4u) {
        if (at < 0x398u) { *sp = y; *cp = 1.0f; return; }
        double x2 = x * x;
        *sp = gsc_sinf_poly(x, x2, 0, 0);
        *cp = gsc_sinf_poly(x, x2, 0, 1);
        return;
    }
    double r  = x * GSC_HPI_INV;
    double rd = rint(r);
    int    n  = (int)rd;
    x = fma(-rd, GSC_HPI, x);
    double x2 = x * x;
    {
        double s = gsc_sign(n & 3);
        int negcos = (n & 2) ? 1 : 0;
        *sp = gsc_sinf_poly(x * s, x2, negcos, n);
    }
    {
        int n1 = n + 1;
        double s = gsc_sign(n1 & 3);
        int negcos = (n1 & 2) ? 1 : 0;
        *cp = gsc_sinf_poly(x * s, x2, negcos, n ^ 1);
    }
}

// ---------------------------------------------------------------------------
// Probe: int64 vs int32 idx_kj
// ---------------------------------------------------------------------------
__global__ void probe_idx_kernel(const int* __restrict__ idx32, int n_check) {
    __shared__ int any_nz;
    if (threadIdx.x == 0) any_nz = 0;
    __syncthreads();
    for (int i = threadIdx.x; i < n_check; i += blockDim.x) {
        if (idx32[2 * i + 1] != 0) any_nz = 1;
    }
    __syncthreads();
    if (threadIdx.x == 0) g_idx_is64 = (any_nz == 0) ? 1 : 0;
}

// ---------------------------------------------------------------------------
// Counting sort of edges by dist (256 bins) -> g_perm, for warp-coherent
// precision branching in rbf_kernel.
// ---------------------------------------------------------------------------
__global__ void zero_hist_kernel() {
    int t = threadIdx.x;
    if (t < 256) g_hist[t] = 0u;
}
__device__ __forceinline__ int dist_bin(float d) {
    int b = (int)((d - 0.1f) * (256.0f / 4.9f));
    return min(255, max(0, b));
}
__global__ void hist_kernel(const float* __restrict__ dist, int E) {
    __shared__ unsigned h[256];
    h[threadIdx.x] = 0u;
    __syncthreads();
    for (int i = blockIdx.x * blockDim.x + threadIdx.x; i < E;
         i += gridDim.x * blockDim.x)
        atomicAdd(&h[dist_bin(dist[i])], 1u);
    __syncthreads();
    if (h[threadIdx.x]) atomicAdd(&g_hist[threadIdx.x], h[threadIdx.x]);
}
__global__ void scan_kernel() {
    __shared__ unsigned tmp[256];
    int t = threadIdx.x;
    unsigned own = g_hist[t];
    tmp[t] = own;
    __syncthreads();
    for (int off = 1; off < 256; off <<= 1) {
        unsigned v = tmp[t];
        __syncthreads();
        if (t >= off) v += tmp[t - off];
        __syncthreads();
        tmp[t] = v;
        __syncthreads();
    }
    g_off[t] = tmp[t] - own;   // exclusive prefix
}
__global__ void scatter_kernel(const float* __restrict__ dist, int E) {
    int i = blockIdx.x * blockDim.x + threadIdx.x;
    if (i >= E) return;
    unsigned pos = atomicAdd(&g_off[dist_bin(dist[i])], 1u);
    g_perm[pos] = i;
}

// ---------------------------------------------------------------------------
// K1: per-edge rbf. Hybrid precision, warp-coherent via dist-sorted perm.
//  - arg <  TH(l): bit-exact reference pipeline (glibc-DP sincos, strict
//    div.rn order) -- garbage-amplified regime must match bit-for-bit
//  - arg >= TH(l): fp32 sincosf + DIVISION-FREE recurrence using
//    inv(arg) = inv_x * (1/z_lk)   (amplification bounded; <=1e-5 deviation)
// ---------------------------------------------------------------------------
__global__ void __launch_bounds__(256) rbf_kernel(
    const float* __restrict__ dist,
    const float* __restrict__ zeros_lk,
    const float* __restrict__ norm_lk,
    int E)
{
    __shared__ float s_z [NSPH * NRAD];
    __shared__ float s_n [NSPH * NRAD];
    __shared__ float s_zi[NSPH * NRAD];
    if (threadIdx.x < NSPH * NRAD) {
        float z = zeros_lk[threadIdx.x];
        s_z [threadIdx.x] = z;
        s_n [threadIdx.x] = norm_lk[threadIdx.x];
        s_zi[threadIdx.x] = __fdiv_rn(1.0f, z);
    }
    __syncthreads();

    int i = blockIdx.x * blockDim.x + threadIdx.x;
    if (i >= E) return;
    int e = g_perm[i];

    float d = dist[e];
    float x = __fmul_rn(d, 0.2f);            // x = dist * (1/CUTOFF)

    // x^5 square-and-multiply (matches lax.integer_pow)
    float x2  = __fmul_rn(x, x);
    float x4  = __fmul_rn(x2, x2);
    float xp0 = __fmul_rn(x4, x);

    // env (strict, no fma) -- 1/x reused as fast-path inv_x
    float inv_x = __fdiv_rn(1.0f, x);
    float t2 = __fmul_rn(-28.0f, xp0);
    float t3 = __fmul_rn(__fmul_rn(48.0f, xp0), x);
    float t4 = __fmul_rn(__fmul_rn(__fmul_rn(-21.0f, xp0), x), x);
    float env = __fadd_rn(__fadd_rn(__fadd_rn(inv_x, t2), t3), t4);

    float* row = g_rbf + (size_t)e * ROW;

    #pragma unroll 1
    for (int l = 0; l < NSPH; ++l) {
        float th = c_th[l];
        float v[NRAD];
        #pragma unroll 1
        for (int r = 0; r < NRAD; ++r) {
            float arg = __fmul_rn(x, s_z[l * NRAD + r]);
            float j;
            if (arg < th) {
                // ---- exact reference path (bit-identical to round 9) ----
                if (l == 0) {
                    float s = gsc_sinf(arg);
                    j = __fdiv_rn(s, arg);
                } else {
                    float s, c;
                    gsc_sincosf(arg, &s, &c);
                    float j0 = __fdiv_rn(s, arg);
                    float jc = __fsub_rn(__fdiv_rn(s, __fmul_rn(arg, arg)),
                                         __fdiv_rn(c, arg));
                    float jm = j0;
                    for (int ii = 2; ii <= l; ++ii) {
                        float coef = __fdiv_rn((float)(2 * ii - 1), arg);
                        float jn = __fsub_rn(__fmul_rn(coef, jc), jm);
                        jm = jc; jc = jn;
                    }
                    j = jc;
                }
            } else {
                // ---- fast fp32 path: zero divisions ----
                float inv = inv_x * s_zi[l * NRAD + r];   // 1/arg (2-rounding)
                if (l == 0) {
                    j = sinf(arg) * inv;
                } else {
                    float s, c;
                    sincosf(arg, &s, &c);                 // libdevice accurate
                    float j0 = s * inv;
                    float jc = (j0 - c) * inv;            // j1
                    float jm = j0;
                    #pragma unroll
                    for (int ii = 2; ii <= 6; ++ii) {
                        if (ii > l) break;
                        float jn = fmaf((float)(2 * ii - 1) * inv, jc, -jm);
                        jm = jc; jc = jn;
                    }
                    j = jc;
                }
            }
            v[r] = __fmul_rn(env, __fmul_rn(s_n[l * NRAD + r], j));
        }
        float2* dst = reinterpret_cast<float2*>(row + l * NRAD);
        dst[0] = make_float2(v[0], v[1]);
        dst[1] = make_float2(v[2], v[3]);
        dst[2] = make_float2(v[4], v[5]);
    }
}

// ---------------------------------------------------------------------------
// K2: per-triplet gather + Legendre * coef + store. (fp32 cosf safe here.)
// ---------------------------------------------------------------------------
__global__ void __launch_bounds__(128) out_kernel(
    const float* __restrict__ angle,
    const int* __restrict__ idx32,
    float* __restrict__ out,
    int T)
{
    int t = blockIdx.x * blockDim.x + threadIdx.x;
    if (t >= T) return;

    int e = g_idx_is64 ? idx32[2 * t] : idx32[t];

    float ct = cosf(angle[t]);
    float P0 = 1.0f;
    float P1 = ct;
    float P2 = __fmul_rn(__fsub_rn(__fmul_rn(__fmul_rn(3.0f,  ct), P1), P0),                   0.5f);
    float P3 = __fmul_rn(__fsub_rn(__fmul_rn(__fmul_rn(5.0f,  ct), P2), __fmul_rn(2.0f, P1)), 0.33333334f);
    float P4 = __fmul_rn(__fsub_rn(__fmul_rn(__fmul_rn(7.0f,  ct), P3), __fmul_rn(3.0f, P2)), 0.25f);
    float P5 = __fmul_rn(__fsub_rn(__fmul_rn(__fmul_rn(9.0f,  ct), P4), __fmul_rn(4.0f, P3)), 0.2f);
    float P6 = __fmul_rn(__fsub_rn(__fmul_rn(__fmul_rn(11.0f, ct), P5), __fmul_rn(5.0f, P4)), 0.16666667f);

    float cbf[NSPH];
    cbf[0] = __fmul_rn(P0, c_coef[0]);
    cbf[1] = __fmul_rn(P1, c_coef[1]);
    cbf[2] = __fmul_rn(P2, c_coef[2]);
    cbf[3] = __fmul_rn(P3, c_coef[3]);
    cbf[4] = __fmul_rn(P4, c_coef[4]);
    cbf[5] = __fmul_rn(P5, c_coef[5]);
    cbf[6] = __fmul_rn(P6, c_coef[6]);

    const float4* src = reinterpret_cast<const float4*>(g_rbf + (size_t)e * ROW);
    float rb[44];
    #pragma unroll
    for (int q = 0; q < 11; ++q) {
        float4 f = src[q];
        rb[4 * q + 0] = f.x;
        rb[4 * q + 1] = f.y;
        rb[4 * q + 2] = f.z;
        rb[4 * q + 3] = f.w;
    }

    float2* o = reinterpret_cast<float2*>(out + (size_t)t * 42);
    #pragma unroll
    for (int q = 0; q < 21; ++q) {
        const int k0 = 2 * q;
        const int k1 = 2 * q + 1;
        o[q] = make_float2(__fmul_rn(rb[k0], cbf[k0 / 6]),
                           __fmul_rn(rb[k1], cbf[k1 / 6]));
    }
}

// ---------------------------------------------------------------------------
// Launch
// ---------------------------------------------------------------------------
extern "C" void kernel_launch(void* const* d_in, const int* in_sizes, int n_in,
                              void* d_out, int out_size)
{
    const float* dist     = (const float*)d_in[0];
    const float* angle    = (const float*)d_in[1];
    const int*   idx32    = (const int*)  d_in[2];
    const float* zeros_lk = (const float*)d_in[3];
    const float* norm_lk  = (const float*)d_in[4];
    float* out = (float*)d_out;

    int E = in_sizes[0];
    int T = in_sizes[1];
    if (E > CAP_E) E = CAP_E;

    int n_check = 2048;
    if (2 * n_check > T) n_check = T / 2;
    probe_idx_kernel<<<1, 256>>>(idx32, n_check);

    // counting sort by dist
    zero_hist_kernel<<<1, 256>>>();
    hist_kernel<<<296, 256>>>(dist, E);
    scan_kernel<<<1, 256>>>();
    scatter_kernel<<<(E + 255) / 256, 256>>>(dist, E);

    rbf_kernel<<<(E + 255) / 256, 256>>>(dist, zeros_lk, norm_lk, E);
    out_kernel<<<(T + 127) / 128, 128>>>(angle, idx32, out, T);
}

// round 12
// speedup vs baseline: 4.3160x; 1.1079x over previous
#include <cuda_runtime.h>
#include <math.h>
#include <stdint.h>

// Problem constants
#define NSPH 7
#define NRAD 6
#define ROW  48          // padded rbf row (42 used), 192 bytes
#define CAP_E 1048576    // capacity for edges (E = 1,000,000)

// Scratch (static device arrays; no allocation)
__device__ float g_rbf[(size_t)CAP_E * ROW];
__device__ int   g_perm[CAP_E];
__device__ unsigned g_hist[256];
__device__ unsigned g_off[256];
__device__ int   g_idx_is64;

// sqrt((2l+1)/(4*pi)) in double, rounded to f32 (matches numpy cast)
__device__ __constant__ float c_coef[NSPH] = {
    (float)0.28209479177387814,
    (float)0.48860251190291992,
    (float)0.63078313050504009,
    (float)0.74635266518023078,
    (float)0.84628437532163443,
    (float)0.93560257962738882,
    (float)1.01710723628205748
};

// exact-path thresholds for l>=2 (turning point: amplification O(1) above arg=l)
__device__ __constant__ float c_th[NSPH] = {0.0f, 0.0f, 2.0f, 3.0f, 4.0f, 5.0f, 6.0f};

// ===========================================================================
// glibc scalar sinf/cosf port (sysdeps/ieee754/flt-32/s_sincosf).
// Bit-exact vs reference (round 9 rel_err == 0.0). Restructured for fewer
// DP-pipe ops: sign multiplies replaced by exact sign-bit XOR
// (sinpoly is odd in x; cos poly ignores the signed argument; fma with all
// coefficients negated == exact negation). Bit-identical outputs.
// ===========================================================================
#define GSC_HPI_INV 0x1.45F306DC9C883p-1   /* 2/pi */
#define GSC_HPI     0x1.921FB54442D18p0    /* pi/2 */
#define GSC_C0  (1.0)
#define GSC_C1  (-0x1.ffffffd0c621cp-2)
#define GSC_C2  ( 0x1.55553e1068f19p-5)
#define GSC_C3  (-0x1.6c087e89a359dp-10)
#define GSC_C4  ( 0x1.99343027bf8c3p-16)
#define GSC_S1  (-0x1.555545995a603p-3)
#define GSC_S2  ( 0x1.1107605230bc4p-7)
#define GSC_S3  (-0x1.994eb3774cf24p-13)

__device__ __forceinline__ unsigned gsc_abstop12(float y) {
    return (__float_as_uint(y) >> 20) & 0x7ffu;
}
__device__ __forceinline__ double gsc_sinpoly(double x, double x2) {
    double x3 = x * x2;
    double s1 = fma(x2, GSC_S3, GSC_S2);
    double x7 = x3 * x2;
    double s  = fma(x3, GSC_S1, x);
    return fma(x7, s1, s);
}
__device__ __forceinline__ double gsc_cospoly(double x2) {
    double x4 = x2 * x2;
    double c2 = fma(x2, GSC_C4, GSC_C3);
    double c1 = fma(x2, GSC_C1, GSC_C0);
    double x6 = x4 * x2;
    double c  = fma(x4, GSC_C2, c1);
    return fma(x6, c2, c);
}
__device__ __forceinline__ float fneg_if(float v, bool neg) {
    return __uint_as_float(__float_as_uint(v) ^ (neg ? 0x80000000u : 0u));
}
// Fused sincos, bit-identical to glibc scalar sinf(y), cosf(y). y > 0 here.
__device__ __forceinline__ void gsc_sincosf2(float y, float* sp, float* cp) {
    double x = (double)y;
    unsigned at = gsc_abstop12(y);
    if (at < 0x3f4u) {
        if (at < 0x398u) { *sp = y; *cp = 1.0f; return; }
        double x2 = x * x;
        *sp = (float)gsc_sinpoly(x, x2);
        *cp = (float)gsc_cospoly(x2);
        return;
    }
    double r  = x * GSC_HPI_INV;
    double rd = rint(r);
    int    n  = (int)rd;
    x = fma(-rd, GSC_HPI, x);
    double x2 = x * x;
    float sv = (float)gsc_sinpoly(x, x2);
    float cv = (float)gsc_cospoly(x2);
    bool odd  = (n & 1) != 0;
    bool flip = (n & 2) != 0;
    if (!odd) {
        *sp = fneg_if(sv, flip);     // n%4==0: +s,+c ; n%4==2: -s,-c
        *cp = fneg_if(cv, flip);
    } else {
        *sp = fneg_if(cv, flip);     // n%4==1: +c,-s ; n%4==3: -c,+s
        *cp = fneg_if(sv, !flip);
    }
}

// ---------------------------------------------------------------------------
// Probe: int64 vs int32 idx_kj
// ---------------------------------------------------------------------------
__global__ void probe_idx_kernel(const int* __restrict__ idx32, int n_check) {
    __shared__ int any_nz;
    if (threadIdx.x == 0) any_nz = 0;
    __syncthreads();
    for (int i = threadIdx.x; i < n_check; i += blockDim.x) {
        if (idx32[2 * i + 1] != 0) any_nz = 1;
    }
    __syncthreads();
    if (threadIdx.x == 0) g_idx_is64 = (any_nz == 0) ? 1 : 0;
}

// ---------------------------------------------------------------------------
// Counting sort of edges by dist (256 bins) -> g_perm (warp-coherent branch)
// ---------------------------------------------------------------------------
__global__ void zero_hist_kernel() {
    int t = threadIdx.x;
    if (t < 256) g_hist[t] = 0u;
}
__device__ __forceinline__ int dist_bin(float d) {
    int b = (int)((d - 0.1f) * (256.0f / 4.9f));
    return min(255, max(0, b));
}
__global__ void hist_kernel(const float* __restrict__ dist, int E) {
    __shared__ unsigned h[256];
    h[threadIdx.x] = 0u;
    __syncthreads();
    for (int i = blockIdx.x * blockDim.x + threadIdx.x; i < E;
         i += gridDim.x * blockDim.x)
        atomicAdd(&h[dist_bin(dist[i])], 1u);
    __syncthreads();
    if (h[threadIdx.x]) atomicAdd(&g_hist[threadIdx.x], h[threadIdx.x]);
}
__global__ void scan_kernel() {
    __shared__ unsigned tmp[256];
    int t = threadIdx.x;
    unsigned own = g_hist[t];
    tmp[t] = own;
    __syncthreads();
    for (int off = 1; off < 256; off <<= 1) {
        unsigned v = tmp[t];
        __syncthreads();
        if (t >= off) v += tmp[t - off];
        __syncthreads();
        tmp[t] = v;
        __syncthreads();
    }
    g_off[t] = tmp[t] - own;
}
__global__ void scatter_kernel(const float* __restrict__ dist, int E) {
    int i = blockIdx.x * blockDim.x + threadIdx.x;
    if (i >= E) return;
    unsigned pos = atomicAdd(&g_off[dist_bin(dist[i])], 1u);
    g_perm[pos] = i;
}

// ---------------------------------------------------------------------------
// K1: per-edge rbf. DP-throughput-bound -> minimize exact (DP) cells:
//  - l=0,1: always fast fp32 (no/bounded amplification)
//  - l>=2, arg <  l: bit-exact glibc-DP path (garbage regime, must match bits)
//  - l>=2, arg >= l: fp32 sincosf + division-free recurrence
// ---------------------------------------------------------------------------
__global__ void __launch_bounds__(256) rbf_kernel(
    const float* __restrict__ dist,
    const float* __restrict__ zeros_lk,
    const float* __restrict__ norm_lk,
    int E)
{
    __shared__ float s_z [NSPH * NRAD];
    __shared__ float s_n [NSPH * NRAD];
    __shared__ float s_zi[NSPH * NRAD];
    if (threadIdx.x < NSPH * NRAD) {
        float z = zeros_lk[threadIdx.x];
        s_z [threadIdx.x] = z;
        s_n [threadIdx.x] = norm_lk[threadIdx.x];
        s_zi[threadIdx.x] = __fdiv_rn(1.0f, z);
    }
    __syncthreads();

    int i = blockIdx.x * blockDim.x + threadIdx.x;
    if (i >= E) return;
    int e = g_perm[i];

    float d = dist[e];
    float x = __fmul_rn(d, 0.2f);            // x = dist * (1/CUTOFF)

    float x2  = __fmul_rn(x, x);
    float x4  = __fmul_rn(x2, x2);
    float xp0 = __fmul_rn(x4, x);

    float inv_x = __fdiv_rn(1.0f, x);
    float t2 = __fmul_rn(-28.0f, xp0);
    float t3 = __fmul_rn(__fmul_rn(48.0f, xp0), x);
    float t4 = __fmul_rn(__fmul_rn(__fmul_rn(-21.0f, xp0), x), x);
    float env = __fadd_rn(__fadd_rn(__fadd_rn(inv_x, t2), t3), t4);

    float* row = g_rbf + (size_t)e * ROW;

    // ---- l = 0: fast everywhere (j0 = sin(z)/z, no amplification) ----
    {
        float v[NRAD];
        #pragma unroll
        for (int r = 0; r < NRAD; ++r) {
            float arg = __fmul_rn(x, s_z[r]);
            float inv = inv_x * s_zi[r];
            float j = sinf(arg) * inv;
            v[r] = __fmul_rn(env, __fmul_rn(s_n[r], j));
        }
        float2* dst = reinterpret_cast<float2*>(row);
        dst[0] = make_float2(v[0], v[1]);
        dst[1] = make_float2(v[2], v[3]);
        dst[2] = make_float2(v[4], v[5]);
    }
    // ---- l = 1: fast everywhere (bounded cancellation) ----
    {
        float v[NRAD];
        #pragma unroll
        for (int r = 0; r < NRAD; ++r) {
            float arg = __fmul_rn(x, s_z[NRAD + r]);
            float inv = inv_x * s_zi[NRAD + r];
            float s, c;
            sincosf(arg, &s, &c);
            float j0 = s * inv;
            float j  = (j0 - c) * inv;
            v[r] = __fmul_rn(env, __fmul_rn(s_n[NRAD + r], j));
        }
        float2* dst = reinterpret_cast<float2*>(row + NRAD);
        dst[0] = make_float2(v[0], v[1]);
        dst[1] = make_float2(v[2], v[3]);
        dst[2] = make_float2(v[4], v[5]);
    }
    // ---- l = 2..6: hybrid ----
    #pragma unroll 1
    for (int l = 2; l < NSPH; ++l) {
        float th = c_th[l];
        float v[NRAD];
        #pragma unroll 1
        for (int r = 0; r < NRAD; ++r) {
            float arg = __fmul_rn(x, s_z[l * NRAD + r]);
            float j;
            if (arg < th) {
                // ---- exact reference path (bit-identical to round 9) ----
                float s, c;
                gsc_sincosf2(arg, &s, &c);
                float j0 = __fdiv_rn(s, arg);
                float jc = __fsub_rn(__fdiv_rn(s, __fmul_rn(arg, arg)),
                                     __fdiv_rn(c, arg));
                float jm = j0;
                for (int ii = 2; ii <= l; ++ii) {
                    float coef = __fdiv_rn((float)(2 * ii - 1), arg);
                    float jn = __fsub_rn(__fmul_rn(coef, jc), jm);
                    jm = jc; jc = jn;
                }
                j = jc;
            } else {
                // ---- fast fp32 path: zero divisions ----
                float inv = inv_x * s_zi[l * NRAD + r];
                float s, c;
                sincosf(arg, &s, &c);
                float j0 = s * inv;
                float jc = (j0 - c) * inv;
                float jm = j0;
                #pragma unroll
                for (int ii = 2; ii <= 6; ++ii) {
                    if (ii > l) break;
                    float jn = fmaf((float)(2 * ii - 1) * inv, jc, -jm);
                    jm = jc; jc = jn;
                }
                j = jc;
            }
            v[r] = __fmul_rn(env, __fmul_rn(s_n[l * NRAD + r], j));
        }
        float2* dst = reinterpret_cast<float2*>(row + l * NRAD);
        dst[0] = make_float2(v[0], v[1]);
        dst[1] = make_float2(v[2], v[3]);
        dst[2] = make_float2(v[4], v[5]);
    }
}

// ---------------------------------------------------------------------------
// K2: per-triplet gather + Legendre * coef + store.
// ---------------------------------------------------------------------------
__global__ void __launch_bounds__(128) out_kernel(
    const float* __restrict__ angle,
    const int* __restrict__ idx32,
    float* __restrict__ out,
    int T)
{
    int t = blockIdx.x * blockDim.x + threadIdx.x;
    if (t >= T) return;

    int e = g_idx_is64 ? idx32[2 * t] : idx32[t];

    float ct = cosf(angle[t]);
    float P0 = 1.0f;
    float P1 = ct;
    float P2 = __fmul_rn(__fsub_rn(__fmul_rn(__fmul_rn(3.0f,  ct), P1), P0),                   0.5f);
    float P3 = __fmul_rn(__fsub_rn(__fmul_rn(__fmul_rn(5.0f,  ct), P2), __fmul_rn(2.0f, P1)), 0.33333334f);
    float P4 = __fmul_rn(__fsub_rn(__fmul_rn(__fmul_rn(7.0f,  ct), P3), __fmul_rn(3.0f, P2)), 0.25f);
    float P5 = __fmul_rn(__fsub_rn(__fmul_rn(__fmul_rn(9.0f,  ct), P4), __fmul_rn(4.0f, P3)), 0.2f);
    float P6 = __fmul_rn(__fsub_rn(__fmul_rn(__fmul_rn(11.0f, ct), P5), __fmul_rn(5.0f, P4)), 0.16666667f);

    float cbf[NSPH];
    cbf[0] = __fmul_rn(P0, c_coef[0]);
    cbf[1] = __fmul_rn(P1, c_coef[1]);
    cbf[2] = __fmul_rn(P2, c_coef[2]);
    cbf[3] = __fmul_rn(P3, c_coef[3]);
    cbf[4] = __fmul_rn(P4, c_coef[4]);
    cbf[5] = __fmul_rn(P5, c_coef[5]);
    cbf[6] = __fmul_rn(P6, c_coef[6]);

    const float4* src = reinterpret_cast<const float4*>(g_rbf + (size_t)e * ROW);
    float rb[44];
    #pragma unroll
    for (int q = 0; q < 11; ++q) {
        float4 f = src[q];
        rb[4 * q + 0] = f.x;
        rb[4 * q + 1] = f.y;
        rb[4 * q + 2] = f.z;
        rb[4 * q + 3] = f.w;
    }

    float2* o = reinterpret_cast<float2*>(out + (size_t)t * 42);
    #pragma unroll
    for (int q = 0; q < 21; ++q) {
        const int k0 = 2 * q;
        const int k1 = 2 * q + 1;
        o[q] = make_float2(__fmul_rn(rb[k0], cbf[k0 / 6]),
                           __fmul_rn(rb[k1], cbf[k1 / 6]));
    }
}

// ---------------------------------------------------------------------------
// Launch
// ---------------------------------------------------------------------------
extern "C" void kernel_launch(void* const* d_in, const int* in_sizes, int n_in,
                              void* d_out, int out_size)
{
    const float* dist     = (const float*)d_in[0];
    const float* angle    = (const float*)d_in[1];
    const int*   idx32    = (const int*)  d_in[2];
    const float* zeros_lk = (const float*)d_in[3];
    const float* norm_lk  = (const float*)d_in[4];
    float* out = (float*)d_out;

    int E = in_sizes[0];
    int T = in_sizes[1];
    if (E > CAP_E) E = CAP_E;

    int n_check = 2048;
    if (2 * n_check > T) n_check = T / 2;
    probe_idx_kernel<<<1, 256>>>(idx32, n_check);

    zero_hist_kernel<<<1, 256>>>();
    hist_kernel<<<296, 256>>>(dist, E);
    scan_kernel<<<1, 256>>>();
    scatter_kernel<<<(E + 255) / 256, 256>>>(dist, E);

    rbf_kernel<<<(E + 255) / 256, 256>>>(dist, zeros_lk, norm_lk, E);
    out_kernel<<<(T + 127) / 128, 128>>>(angle, idx32, out, T);
}

// round 13
// speedup vs baseline: 4.7655x; 1.1041x over previous
#include <cuda_runtime.h>
#include <math.h>
#include <stdint.h>

// Problem constants
#define NSPH 7
#define NRAD 6
#define ROW  48          // padded rbf row (42 used), 192 bytes
#define CAP_E 1048576    // capacity for edges (E = 1,000,000)

// Scratch (static device arrays; no allocation)
__device__ float g_rbf[(size_t)CAP_E * ROW];
__device__ int   g_perm[CAP_E];
__device__ unsigned g_hist[256];
__device__ unsigned g_off[256];
__device__ int   g_idx_is64;

// sqrt((2l+1)/(4*pi)) in double, rounded to f32 (matches numpy cast)
__device__ __constant__ float c_coef[NSPH] = {
    (float)0.28209479177387814,
    (float)0.48860251190291992,
    (float)0.63078313050504009,
    (float)0.74635266518023078,
    (float)0.84628437532163443,
    (float)0.93560257962738882,
    (float)1.01710723628205748
};

// exact-path thresholds: only where garbage amplification R(l,arg) > ~1e4
// does the pipeline need bit-exactness. TH ~= 0.55-0.6 * l.
__device__ __constant__ float c_th[NSPH] = {0.0f, 0.0f, 1.0f, 1.6f, 2.2f, 2.9f, 3.6f};

// ===========================================================================
// glibc scalar sinf/cosf port (sysdeps/ieee754/flt-32/s_sincosf).
// Bit-exact vs reference (round 9 rel_err == 0.0). Sign handling via exact
// sign-bit XOR (bit-identical to the multiply form).
// ===========================================================================
#define GSC_HPI_INV 0x1.45F306DC9C883p-1   /* 2/pi */
#define GSC_HPI     0x1.921FB54442D18p0    /* pi/2 */
#define GSC_C0  (1.0)
#define GSC_C1  (-0x1.ffffffd0c621cp-2)
#define GSC_C2  ( 0x1.55553e1068f19p-5)
#define GSC_C3  (-0x1.6c087e89a359dp-10)
#define GSC_C4  ( 0x1.99343027bf8c3p-16)
#define GSC_S1  (-0x1.555545995a603p-3)
#define GSC_S2  ( 0x1.1107605230bc4p-7)
#define GSC_S3  (-0x1.994eb3774cf24p-13)

__device__ __forceinline__ unsigned gsc_abstop12(float y) {
    return (__float_as_uint(y) >> 20) & 0x7ffu;
}
__device__ __forceinline__ double gsc_sinpoly(double x, double x2) {
    double x3 = x * x2;
    double s1 = fma(x2, GSC_S3, GSC_S2);
    double x7 = x3 * x2;
    double s  = fma(x3, GSC_S1, x);
    return fma(x7, s1, s);
}
__device__ __forceinline__ double gsc_cospoly(double x2) {
    double x4 = x2 * x2;
    double c2 = fma(x2, GSC_C4, GSC_C3);
    double c1 = fma(x2, GSC_C1, GSC_C0);
    double x6 = x4 * x2;
    double c  = fma(x4, GSC_C2, c1);
    return fma(x6, c2, c);
}
__device__ __forceinline__ float fneg_if(float v, bool neg) {
    return __uint_as_float(__float_as_uint(v) ^ (neg ? 0x80000000u : 0u));
}
// Fused sincos, bit-identical to glibc scalar sinf(y), cosf(y). y > 0 here.
__device__ __forceinline__ void gsc_sincosf2(float y, float* sp, float* cp) {
    double x = (double)y;
    unsigned at = gsc_abstop12(y);
    if (at < 0x3f4u) {
        if (at < 0x398u) { *sp = y; *cp = 1.0f; return; }
        double x2 = x * x;
        *sp = (float)gsc_sinpoly(x, x2);
        *cp = (float)gsc_cospoly(x2);
        return;
    }
    double r  = x * GSC_HPI_INV;
    double rd = rint(r);
    int    n  = (int)rd;
    x = fma(-rd, GSC_HPI, x);
    double x2 = x * x;
    float sv = (float)gsc_sinpoly(x, x2);
    float cv = (float)gsc_cospoly(x2);
    bool odd  = (n & 1) != 0;
    bool flip = (n & 2) != 0;
    if (!odd) {
        *sp = fneg_if(sv, flip);
        *cp = fneg_if(cv, flip);
    } else {
        *sp = fneg_if(cv, flip);
        *cp = fneg_if(sv, !flip);
    }
}

// ---------------------------------------------------------------------------
// Probe: int64 vs int32 idx_kj
// ---------------------------------------------------------------------------
__global__ void probe_idx_kernel(const int* __restrict__ idx32, int n_check) {
    __shared__ int any_nz;
    if (threadIdx.x == 0) any_nz = 0;
    __syncthreads();
    for (int i = threadIdx.x; i < n_check; i += blockDim.x) {
        if (idx32[2 * i + 1] != 0) any_nz = 1;
    }
    __syncthreads();
    if (threadIdx.x == 0) g_idx_is64 = (any_nz == 0) ? 1 : 0;
}

// ---------------------------------------------------------------------------
// Counting sort of edges by dist (256 bins) -> g_perm (warp-coherent branch)
// ---------------------------------------------------------------------------
__global__ void zero_hist_kernel() {
    int t = threadIdx.x;
    if (t < 256) g_hist[t] = 0u;
}
__device__ __forceinline__ int dist_bin(float d) {
    int b = (int)((d - 0.1f) * (256.0f / 4.9f));
    return min(255, max(0, b));
}
__global__ void hist_kernel(const float* __restrict__ dist, int E) {
    __shared__ unsigned h[256];
    h[threadIdx.x] = 0u;
    __syncthreads();
    for (int i = blockIdx.x * blockDim.x + threadIdx.x; i < E;
         i += gridDim.x * blockDim.x)
        atomicAdd(&h[dist_bin(dist[i])], 1u);
    __syncthreads();
    if (h[threadIdx.x]) atomicAdd(&g_hist[threadIdx.x], h[threadIdx.x]);
}
__global__ void scan_kernel() {
    __shared__ unsigned tmp[256];
    int t = threadIdx.x;
    unsigned own = g_hist[t];
    tmp[t] = own;
    __syncthreads();
    for (int off = 1; off < 256; off <<= 1) {
        unsigned v = tmp[t];
        __syncthreads();
        if (t >= off) v += tmp[t - off];
        __syncthreads();
        tmp[t] = v;
        __syncthreads();
    }
    g_off[t] = tmp[t] - own;
}
__global__ void scatter_kernel(const float* __restrict__ dist, int E) {
    int i = blockIdx.x * blockDim.x + threadIdx.x;
    if (i >= E) return;
    unsigned pos = atomicAdd(&g_off[dist_bin(dist[i])], 1u);
    g_perm[pos] = i;
}

// ---------------------------------------------------------------------------
// K1: per-edge rbf. DP-throughput-bound -> minimize exact (DP) cells:
//  - l=0,1: always fast fp32
//  - l>=2, arg <  TH(l) (~0.6 l): bit-exact glibc-DP path (garbage regime)
//  - l>=2, arg >= TH(l): fp32 sincosf + division-free recurrence
// ---------------------------------------------------------------------------
__global__ void __launch_bounds__(256) rbf_kernel(
    const float* __restrict__ dist,
    const float* __restrict__ zeros_lk,
    const float* __restrict__ norm_lk,
    int E)
{
    __shared__ float s_z [NSPH * NRAD];
    __shared__ float s_n [NSPH * NRAD];
    __shared__ float s_zi[NSPH * NRAD];
    if (threadIdx.x < NSPH * NRAD) {
        float z = zeros_lk[threadIdx.x];
        s_z [threadIdx.x] = z;
        s_n [threadIdx.x] = norm_lk[threadIdx.x];
        s_zi[threadIdx.x] = __fdiv_rn(1.0f, z);
    }
    __syncthreads();

    int i = blockIdx.x * blockDim.x + threadIdx.x;
    if (i >= E) return;
    int e = g_perm[i];

    float d = dist[e];
    float x = __fmul_rn(d, 0.2f);            // x = dist * (1/CUTOFF)

    float x2  = __fmul_rn(x, x);
    float x4  = __fmul_rn(x2, x2);
    float xp0 = __fmul_rn(x4, x);

    float inv_x = __fdiv_rn(1.0f, x);
    float t2 = __fmul_rn(-28.0f, xp0);
    float t3 = __fmul_rn(__fmul_rn(48.0f, xp0), x);
    float t4 = __fmul_rn(__fmul_rn(__fmul_rn(-21.0f, xp0), x), x);
    float env = __fadd_rn(__fadd_rn(__fadd_rn(inv_x, t2), t3), t4);

    float* row = g_rbf + (size_t)e * ROW;

    // ---- l = 0: fast everywhere ----
    {
        float v[NRAD];
        #pragma unroll
        for (int r = 0; r < NRAD; ++r) {
            float arg = __fmul_rn(x, s_z[r]);
            float inv = inv_x * s_zi[r];
            float j = sinf(arg) * inv;
            v[r] = __fmul_rn(env, __fmul_rn(s_n[r], j));
        }
        float2* dst = reinterpret_cast<float2*>(row);
        dst[0] = make_float2(v[0], v[1]);
        dst[1] = make_float2(v[2], v[3]);
        dst[2] = make_float2(v[4], v[5]);
    }
    // ---- l = 1: fast everywhere ----
    {
        float v[NRAD];
        #pragma unroll
        for (int r = 0; r < NRAD; ++r) {
            float arg = __fmul_rn(x, s_z[NRAD + r]);
            float inv = inv_x * s_zi[NRAD + r];
            float s, c;
            sincosf(arg, &s, &c);
            float j0 = s * inv;
            float j  = (j0 - c) * inv;
            v[r] = __fmul_rn(env, __fmul_rn(s_n[NRAD + r], j));
        }
        float2* dst = reinterpret_cast<float2*>(row + NRAD);
        dst[0] = make_float2(v[0], v[1]);
        dst[1] = make_float2(v[2], v[3]);
        dst[2] = make_float2(v[4], v[5]);
    }
    // ---- l = 2..6: hybrid ----
    #pragma unroll 1
    for (int l = 2; l < NSPH; ++l) {
        float th = c_th[l];
        float v[NRAD];
        #pragma unroll 1
        for (int r = 0; r < NRAD; ++r) {
            float arg = __fmul_rn(x, s_z[l * NRAD + r]);
            float j;
            if (arg < th) {
                // ---- exact reference path (bit-identical to round 9) ----
                float s, c;
                gsc_sincosf2(arg, &s, &c);
                float j0 = __fdiv_rn(s, arg);
                float jc = __fsub_rn(__fdiv_rn(s, __fmul_rn(arg, arg)),
                                     __fdiv_rn(c, arg));
                float jm = j0;
                for (int ii = 2; ii <= l; ++ii) {
                    float coef = __fdiv_rn((float)(2 * ii - 1), arg);
                    float jn = __fsub_rn(__fmul_rn(coef, jc), jm);
                    jm = jc; jc = jn;
                }
                j = jc;
            } else {
                // ---- fast fp32 path: zero divisions ----
                float inv = inv_x * s_zi[l * NRAD + r];
                float s, c;
                sincosf(arg, &s, &c);
                float j0 = s * inv;
                float jc = (j0 - c) * inv;
                float jm = j0;
                #pragma unroll
                for (int ii = 2; ii <= 6; ++ii) {
                    if (ii > l) break;
                    float jn = fmaf((float)(2 * ii - 1) * inv, jc, -jm);
                    jm = jc; jc = jn;
                }
                j = jc;
            }
            v[r] = __fmul_rn(env, __fmul_rn(s_n[l * NRAD + r], j));
        }
        float2* dst = reinterpret_cast<float2*>(row + l * NRAD);
        dst[0] = make_float2(v[0], v[1]);
        dst[1] = make_float2(v[2], v[3]);
        dst[2] = make_float2(v[4], v[5]);
    }
}

// ---------------------------------------------------------------------------
// K2: per-triplet gather + Legendre * coef + store.
// ---------------------------------------------------------------------------
__global__ void __launch_bounds__(128) out_kernel(
    const float* __restrict__ angle,
    const int* __restrict__ idx32,
    float* __restrict__ out,
    int T)
{
    int t = blockIdx.x * blockDim.x + threadIdx.x;
    if (t >= T) return;

    int e = g_idx_is64 ? idx32[2 * t] : idx32[t];

    float ct = cosf(angle[t]);
    float P0 = 1.0f;
    float P1 = ct;
    float P2 = __fmul_rn(__fsub_rn(__fmul_rn(__fmul_rn(3.0f,  ct), P1), P0),                   0.5f);
    float P3 = __fmul_rn(__fsub_rn(__fmul_rn(__fmul_rn(5.0f,  ct), P2), __fmul_rn(2.0f, P1)), 0.33333334f);
    float P4 = __fmul_rn(__fsub_rn(__fmul_rn(__fmul_rn(7.0f,  ct), P3), __fmul_rn(3.0f, P2)), 0.25f);
    float P5 = __fmul_rn(__fsub_rn(__fmul_rn(__fmul_rn(9.0f,  ct), P4), __fmul_rn(4.0f, P3)), 0.2f);
    float P6 = __fmul_rn(__fsub_rn(__fmul_rn(__fmul_rn(11.0f, ct), P5), __fmul_rn(5.0f, P4)), 0.16666667f);

    float cbf[NSPH];
    cbf[0] = __fmul_rn(P0, c_coef[0]);
    cbf[1] = __fmul_rn(P1, c_coef[1]);
    cbf[2] = __fmul_rn(P2, c_coef[2]);
    cbf[3] = __fmul_rn(P3, c_coef[3]);
    cbf[4] = __fmul_rn(P4, c_coef[4]);
    cbf[5] = __fmul_rn(P5, c_coef[5]);
    cbf[6] = __fmul_rn(P6, c_coef[6]);

    const float4* src = reinterpret_cast<const float4*>(g_rbf + (size_t)e * ROW);
    float rb[44];
    #pragma unroll
    for (int q = 0; q < 11; ++q) {
        float4 f = src[q];
        rb[4 * q + 0] = f.x;
        rb[4 * q + 1] = f.y;
        rb[4 * q + 2] = f.z;
        rb[4 * q + 3] = f.w;
    }

    float2* o = reinterpret_cast<float2*>(out + (size_t)t * 42);
    #pragma unroll
    for (int q = 0; q < 21; ++q) {
        const int k0 = 2 * q;
        const int k1 = 2 * q + 1;
        o[q] = make_float2(__fmul_rn(rb[k0], cbf[k0 / 6]),
                           __fmul_rn(rb[k1], cbf[k1 / 6]));
    }
}

// ---------------------------------------------------------------------------
// Launch
// ---------------------------------------------------------------------------
extern "C" void kernel_launch(void* const* d_in, const int* in_sizes, int n_in,
                              void* d_out, int out_size)
{
    const float* dist     = (const float*)d_in[0];
    const float* angle    = (const float*)d_in[1];
    const int*   idx32    = (const int*)  d_in[2];
    const float* zeros_lk = (const float*)d_in[3];
    const float* norm_lk  = (const float*)d_in[4];
    float* out = (float*)d_out;

    int E = in_sizes[0];
    int T = in_sizes[1];
    if (E > CAP_E) E = CAP_E;

    int n_check = 2048;
    if (2 * n_check > T) n_check = T / 2;
    probe_idx_kernel<<<1, 256>>>(idx32, n_check);

    zero_hist_kernel<<<1, 256>>>();
    hist_kernel<<<296, 256>>>(dist, E);
    scan_kernel<<<1, 256>>>();
    scatter_kernel<<<(E + 255) / 256, 256>>>(dist, E);

    rbf_kernel<<<(E + 255) / 256, 256>>>(dist, zeros_lk, norm_lk, E);
    out_kernel<<<(T + 127) / 128, 128>>>(angle, idx32, out, T);
}

// round 14
// speedup vs baseline: 4.7703x; 1.0010x over previous
#include <cuda_runtime.h>
#include <math.h>
#include <stdint.h>

// Problem constants
#define NSPH 7
#define NRAD 6
#define ROW  48          // padded rbf row (42 used), 192 bytes
#define CAP_E 1048576    // capacity for edges (E = 1,000,000)

// Scratch (static device arrays; no allocation)
__device__ float g_rbf[(size_t)CAP_E * ROW];
__device__ int   g_perm[CAP_E];
__device__ unsigned g_hist[256];
__device__ unsigned g_off[256];
__device__ int   g_idx_is64;

// sqrt((2l+1)/(4*pi)) in double, rounded to f32 (matches numpy cast)
__device__ __constant__ float c_coef[NSPH] = {
    (float)0.28209479177387814,
    (float)0.48860251190291992,
    (float)0.63078313050504009,
    (float)0.74635266518023078,
    (float)0.84628437532163443,
    (float)0.93560257962738882,
    (float)1.01710723628205748
};

// tier thresholds: below c_th -> bit-exact DP path (R>~85);
// [c_th, c_th2) -> accurate fp32 sincosf (R in (6,85]);
// >= c_th2 -> MUFU __sincosf (R<6, eps 2.4e-6 -> <1.5e-5 abs)
__device__ __constant__ float c_th [NSPH] = {0.0f, 0.0f, 1.0f, 1.6f, 2.2f, 2.9f, 3.6f};
__device__ __constant__ float c_th2[NSPH] = {0.0f, 0.5f, 1.5f, 2.4f, 3.3f, 4.35f, 5.4f};

// ===========================================================================
// glibc scalar sinf/cosf port (sysdeps/ieee754/flt-32/s_sincosf).
// Bit-exact vs reference (round 9 rel_err == 0.0).
// ===========================================================================
#define GSC_HPI_INV 0x1.45F306DC9C883p-1   /* 2/pi */
#define GSC_HPI     0x1.921FB54442D18p0    /* pi/2 */
#define GSC_C0  (1.0)
#define GSC_C1  (-0x1.ffffffd0c621cp-2)
#define GSC_C2  ( 0x1.55553e1068f19p-5)
#define GSC_C3  (-0x1.6c087e89a359dp-10)
#define GSC_C4  ( 0x1.99343027bf8c3p-16)
#define GSC_S1  (-0x1.555545995a603p-3)
#define GSC_S2  ( 0x1.1107605230bc4p-7)
#define GSC_S3  (-0x1.994eb3774cf24p-13)

__device__ __forceinline__ unsigned gsc_abstop12(float y) {
    return (__float_as_uint(y) >> 20) & 0x7ffu;
}
__device__ __forceinline__ double gsc_sinpoly(double x, double x2) {
    double x3 = x * x2;
    double s1 = fma(x2, GSC_S3, GSC_S2);
    double x7 = x3 * x2;
    double s  = fma(x3, GSC_S1, x);
    return fma(x7, s1, s);
}
__device__ __forceinline__ double gsc_cospoly(double x2) {
    double x4 = x2 * x2;
    double c2 = fma(x2, GSC_C4, GSC_C3);
    double c1 = fma(x2, GSC_C1, GSC_C0);
    double x6 = x4 * x2;
    double c  = fma(x4, GSC_C2, c1);
    return fma(x6, c2, c);
}
__device__ __forceinline__ float fneg_if(float v, bool neg) {
    return __uint_as_float(__float_as_uint(v) ^ (neg ? 0x80000000u : 0u));
}
// Fused sincos, bit-identical to glibc scalar sinf(y), cosf(y). y > 0 here.
__device__ __forceinline__ void gsc_sincosf2(float y, float* sp, float* cp) {
    double x = (double)y;
    unsigned at = gsc_abstop12(y);
    if (at < 0x3f4u) {
        if (at < 0x398u) { *sp = y; *cp = 1.0f; return; }
        double x2 = x * x;
        *sp = (float)gsc_sinpoly(x, x2);
        *cp = (float)gsc_cospoly(x2);
        return;
    }
    double r  = x * GSC_HPI_INV;
    double rd = rint(r);
    int    n  = (int)rd;
    x = fma(-rd, GSC_HPI, x);
    double x2 = x * x;
    float sv = (float)gsc_sinpoly(x, x2);
    float cv = (float)gsc_cospoly(x2);
    bool odd  = (n & 1) != 0;
    bool flip = (n & 2) != 0;
    if (!odd) {
        *sp = fneg_if(sv, flip);
        *cp = fneg_if(cv, flip);
    } else {
        *sp = fneg_if(cv, flip);
        *cp = fneg_if(sv, !flip);
    }
}

// ---------------------------------------------------------------------------
// Probe: int64 vs int32 idx_kj
// ---------------------------------------------------------------------------
__global__ void probe_idx_kernel(const int* __restrict__ idx32, int n_check) {
    __shared__ int any_nz;
    if (threadIdx.x == 0) any_nz = 0;
    __syncthreads();
    for (int i = threadIdx.x; i < n_check; i += blockDim.x) {
        if (idx32[2 * i + 1] != 0) any_nz = 1;
    }
    __syncthreads();
    if (threadIdx.x == 0) g_idx_is64 = (any_nz == 0) ? 1 : 0;
}

// ---------------------------------------------------------------------------
// Counting sort of edges by dist (256 bins) -> g_perm (warp-coherent tiers)
// ---------------------------------------------------------------------------
__global__ void zero_hist_kernel() {
    int t = threadIdx.x;
    if (t < 256) g_hist[t] = 0u;
}
__device__ __forceinline__ int dist_bin(float d) {
    int b = (int)((d - 0.1f) * (256.0f / 4.9f));
    return min(255, max(0, b));
}
__global__ void hist_kernel(const float* __restrict__ dist, int E) {
    __shared__ unsigned h[256];
    h[threadIdx.x] = 0u;
    __syncthreads();
    for (int i = blockIdx.x * blockDim.x + threadIdx.x; i < E;
         i += gridDim.x * blockDim.x)
        atomicAdd(&h[dist_bin(dist[i])], 1u);
    __syncthreads();
    if (h[threadIdx.x]) atomicAdd(&g_hist[threadIdx.x], h[threadIdx.x]);
}
__global__ void scan_kernel() {
    __shared__ unsigned tmp[256];
    int t = threadIdx.x;
    unsigned own = g_hist[t];
    tmp[t] = own;
    __syncthreads();
    for (int off = 1; off < 256; off <<= 1) {
        unsigned v = tmp[t];
        __syncthreads();
        if (t >= off) v += tmp[t - off];
        __syncthreads();
        tmp[t] = v;
        __syncthreads();
    }
    g_off[t] = tmp[t] - own;
}
__global__ void scatter_kernel(const float* __restrict__ dist, int E) {
    int i = blockIdx.x * blockDim.x + threadIdx.x;
    if (i >= E) return;
    unsigned pos = atomicAdd(&g_off[dist_bin(dist[i])], 1u);
    g_perm[pos] = i;
}

// ---------------------------------------------------------------------------
// K1: per-edge rbf. Three-tier precision (warp-coherent via dist sort):
//  exact DP (garbage regime) / accurate fp32 sincosf (moderate R) /
//  MUFU __sincosf (R small -> 2.4e-6 sin error invisible)
// ---------------------------------------------------------------------------
__global__ void __launch_bounds__(256) rbf_kernel(
    const float* __restrict__ dist,
    const float* __restrict__ zeros_lk,
    const float* __restrict__ norm_lk,
    int E)
{
    __shared__ float s_z [NSPH * NRAD];
    __shared__ float s_n [NSPH * NRAD];
    __shared__ float s_zi[NSPH * NRAD];
    if (threadIdx.x < NSPH * NRAD) {
        float z = zeros_lk[threadIdx.x];
        s_z [threadIdx.x] = z;
        s_n [threadIdx.x] = norm_lk[threadIdx.x];
        s_zi[threadIdx.x] = __fdiv_rn(1.0f, z);
    }
    __syncthreads();

    int i = blockIdx.x * blockDim.x + threadIdx.x;
    if (i >= E) return;
    int e = g_perm[i];

    float d = dist[e];
    float x = __fmul_rn(d, 0.2f);            // x = dist * (1/CUTOFF)

    float x2  = __fmul_rn(x, x);
    float x4  = __fmul_rn(x2, x2);
    float xp0 = __fmul_rn(x4, x);

    float inv_x = __fdiv_rn(1.0f, x);
    float t2 = __fmul_rn(-28.0f, xp0);
    float t3 = __fmul_rn(__fmul_rn(48.0f, xp0), x);
    float t4 = __fmul_rn(__fmul_rn(__fmul_rn(-21.0f, xp0), x), x);
    float env = __fadd_rn(__fadd_rn(__fadd_rn(inv_x, t2), t3), t4);

    float* row = g_rbf + (size_t)e * ROW;

    // ---- l = 0: MUFU everywhere (j0 = sin/z, no amplification) ----
    {
        float v[NRAD];
        #pragma unroll
        for (int r = 0; r < NRAD; ++r) {
            float arg = __fmul_rn(x, s_z[r]);
            float inv = inv_x * s_zi[r];
            float j = __sinf(arg) * inv;
            v[r] = __fmul_rn(env, __fmul_rn(s_n[r], j));
        }
        float2* dst = reinterpret_cast<float2*>(row);
        dst[0] = make_float2(v[0], v[1]);
        dst[1] = make_float2(v[2], v[3]);
        dst[2] = make_float2(v[4], v[5]);
    }
    // ---- l = 1: accurate below 0.5, MUFU above ----
    {
        float th2 = c_th2[1];
        float v[NRAD];
        #pragma unroll
        for (int r = 0; r < NRAD; ++r) {
            float arg = __fmul_rn(x, s_z[NRAD + r]);
            float inv = inv_x * s_zi[NRAD + r];
            float s, c;
            if (arg < th2) sincosf(arg, &s, &c);
            else           __sincosf(arg, &s, &c);
            float j0 = s * inv;
            float j  = (j0 - c) * inv;
            v[r] = __fmul_rn(env, __fmul_rn(s_n[NRAD + r], j));
        }
        float2* dst = reinterpret_cast<float2*>(row + NRAD);
        dst[0] = make_float2(v[0], v[1]);
        dst[1] = make_float2(v[2], v[3]);
        dst[2] = make_float2(v[4], v[5]);
    }
    // ---- l = 2..6: three tiers ----
    #pragma unroll 1
    for (int l = 2; l < NSPH; ++l) {
        float th  = c_th[l];
        float th2 = c_th2[l];
        float v[NRAD];
        #pragma unroll 1
        for (int r = 0; r < NRAD; ++r) {
            float arg = __fmul_rn(x, s_z[l * NRAD + r]);
            float j;
            if (arg < th) {
                // ---- exact reference path (bit-identical to round 9) ----
                float s, c;
                gsc_sincosf2(arg, &s, &c);
                float j0 = __fdiv_rn(s, arg);
                float jc = __fsub_rn(__fdiv_rn(s, __fmul_rn(arg, arg)),
                                     __fdiv_rn(c, arg));
                float jm = j0;
                for (int ii = 2; ii <= l; ++ii) {
                    float coef = __fdiv_rn((float)(2 * ii - 1), arg);
                    float jn = __fsub_rn(__fmul_rn(coef, jc), jm);
                    jm = jc; jc = jn;
                }
                j = jc;
            } else {
                // ---- fast fp32 path: zero divisions ----
                float inv = inv_x * s_zi[l * NRAD + r];
                float s, c;
                if (arg < th2) sincosf(arg, &s, &c);      // accurate tier
                else           __sincosf(arg, &s, &c);    // MUFU tier
                float j0 = s * inv;
                float jc = (j0 - c) * inv;
                float jm = j0;
                #pragma unroll
                for (int ii = 2; ii <= 6; ++ii) {
                    if (ii > l) break;
                    float jn = fmaf((float)(2 * ii - 1) * inv, jc, -jm);
                    jm = jc; jc = jn;
                }
                j = jc;
            }
            v[r] = __fmul_rn(env, __fmul_rn(s_n[l * NRAD + r], j));
        }
        float2* dst = reinterpret_cast<float2*>(row + l * NRAD);
        dst[0] = make_float2(v[0], v[1]);
        dst[1] = make_float2(v[2], v[3]);
        dst[2] = make_float2(v[4], v[5]);
    }
}

// ---------------------------------------------------------------------------
// K2: per-triplet gather + Legendre * coef + store.
// ---------------------------------------------------------------------------
__global__ void __launch_bounds__(128) out_kernel(
    const float* __restrict__ angle,
    const int* __restrict__ idx32,
    float* __restrict__ out,
    int T)
{
    int t = blockIdx.x * blockDim.x + threadIdx.x;
    if (t >= T) return;

    int e = g_idx_is64 ? idx32[2 * t] : idx32[t];

    float ct = cosf(angle[t]);
    float P0 = 1.0f;
    float P1 = ct;
    float P2 = __fmul_rn(__fsub_rn(__fmul_rn(__fmul_rn(3.0f,  ct), P1), P0),                   0.5f);
    float P3 = __fmul_rn(__fsub_rn(__fmul_rn(__fmul_rn(5.0f,  ct), P2), __fmul_rn(2.0f, P1)), 0.33333334f);
    float P4 = __fmul_rn(__fsub_rn(__fmul_rn(__fmul_rn(7.0f,  ct), P3), __fmul_rn(3.0f, P2)), 0.25f);
    float P5 = __fmul_rn(__fsub_rn(__fmul_rn(__fmul_rn(9.0f,  ct), P4), __fmul_rn(4.0f, P3)), 0.2f);
    float P6 = __fmul_rn(__fsub_rn(__fmul_rn(__fmul_rn(11.0f, ct), P5), __fmul_rn(5.0f, P4)), 0.16666667f);

    float cbf[NSPH];
    cbf[0] = __fmul_rn(P0, c_coef[0]);
    cbf[1] = __fmul_rn(P1, c_coef[1]);
    cbf[2] = __fmul_rn(P2, c_coef[2]);
    cbf[3] = __fmul_rn(P3, c_coef[3]);
    cbf[4] = __fmul_rn(P4, c_coef[4]);
    cbf[5] = __fmul_rn(P5, c_coef[5]);
    cbf[6] = __fmul_rn(P6, c_coef[6]);

    const float4* src = reinterpret_cast<const float4*>(g_rbf + (size_t)e * ROW);
    float rb[44];
    #pragma unroll
    for (int q = 0; q < 11; ++q) {
        float4 f = src[q];
        rb[4 * q + 0] = f.x;
        rb[4 * q + 1] = f.y;
        rb[4 * q + 2] = f.z;
        rb[4 * q + 3] = f.w;
    }

    float2* o = reinterpret_cast<float2*>(out + (size_t)t * 42);
    #pragma unroll
    for (int q = 0; q < 21; ++q) {
        const int k0 = 2 * q;
        const int k1 = 2 * q + 1;
        o[q] = make_float2(__fmul_rn(rb[k0], cbf[k0 / 6]),
                           __fmul_rn(rb[k1], cbf[k1 / 6]));
    }
}

// ---------------------------------------------------------------------------
// Launch
// ---------------------------------------------------------------------------
extern "C" void kernel_launch(void* const* d_in, const int* in_sizes, int n_in,
                              void* d_out, int out_size)
{
    const float* dist     = (const float*)d_in[0];
    const float* angle    = (const float*)d_in[1];
    const int*   idx32    = (const int*)  d_in[2];
    const float* zeros_lk = (const float*)d_in[3];
    const float* norm_lk  = (const float*)d_in[4];
    float* out = (float*)d_out;

    int E = in_sizes[0];
    int T = in_sizes[1];
    if (E > CAP_E) E = CAP_E;

    int n_check = 2048;
    if (2 * n_check > T) n_check = T / 2;
    probe_idx_kernel<<<1, 256>>>(idx32, n_check);

    zero_hist_kernel<<<1, 256>>>();
    hist_kernel<<<296, 256>>>(dist, E);
    scan_kernel<<<1, 256>>>();
    scatter_kernel<<<(E + 255) / 256, 256>>>(dist, E);

    rbf_kernel<<<(E + 255) / 256, 256>>>(dist, zeros_lk, norm_lk, E);
    out_kernel<<<(T + 127) / 128, 128>>>(angle, idx32, out, T);
}

// round 15
// speedup vs baseline: 6.0745x; 1.2734x over previous
#include <cuda_runtime.h>
#include <math.h>
#include <stdint.h>

// Problem constants
#define NSPH 7
#define NRAD 6
#define ROW  48          // padded rbf row (42 used), 192 bytes
#define CAP_E 1048576    // capacity for edges (E = 1,000,000)

// Scratch (static device arrays; no allocation)
__device__ float g_rbf[(size_t)CAP_E * ROW];   // indexed by SORTED position
__device__ int   g_perm[CAP_E];                // sorted pos -> edge
__device__ int   g_inv [CAP_E];                // edge -> sorted pos
__device__ unsigned g_hist[256];
__device__ unsigned g_off[256];
__device__ int   g_idx_is64;

// sqrt((2l+1)/(4*pi)) in double, rounded to f32 (matches numpy cast)
__device__ __constant__ float c_coef[NSPH] = {
    (float)0.28209479177387814,
    (float)0.48860251190291992,
    (float)0.63078313050504009,
    (float)0.74635266518023078,
    (float)0.84628437532163443,
    (float)0.93560257962738882,
    (float)1.01710723628205748
};

// tiers: arg < th -> bit-exact DP; [th, th2) -> accurate sincosf; else MUFU
__device__ __constant__ float c_th [NSPH] = {0.0f, 0.0f, 0.60f, 1.00f, 1.45f, 1.95f, 2.45f};
__device__ __constant__ float c_th2[NSPH] = {0.0f, 0.50f, 1.25f, 1.70f, 2.20f, 2.75f, 3.30f};

// ===========================================================================
// glibc scalar sinf/cosf port (bit-exact vs reference, round 9 rel_err==0)
// ===========================================================================
#define GSC_HPI_INV 0x1.45F306DC9C883p-1
#define GSC_HPI     0x1.921FB54442D18p0
#define GSC_C0  (1.0)
#define GSC_C1  (-0x1.ffffffd0c621cp-2)
#define GSC_C2  ( 0x1.55553e1068f19p-5)
#define GSC_C3  (-0x1.6c087e89a359dp-10)
#define GSC_C4  ( 0x1.99343027bf8c3p-16)
#define GSC_S1  (-0x1.555545995a603p-3)
#define GSC_S2  ( 0x1.1107605230bc4p-7)
#define GSC_S3  (-0x1.994eb3774cf24p-13)

__device__ __forceinline__ unsigned gsc_abstop12(float y) {
    return (__float_as_uint(y) >> 20) & 0x7ffu;
}
__device__ __forceinline__ double gsc_sinpoly(double x, double x2) {
    double x3 = x * x2;
    double s1 = fma(x2, GSC_S3, GSC_S2);
    double x7 = x3 * x2;
    double s  = fma(x3, GSC_S1, x);
    return fma(x7, s1, s);
}
__device__ __forceinline__ double gsc_cospoly(double x2) {
    double x4 = x2 * x2;
    double c2 = fma(x2, GSC_C4, GSC_C3);
    double c1 = fma(x2, GSC_C1, GSC_C0);
    double x6 = x4 * x2;
    double c  = fma(x4, GSC_C2, c1);
    return fma(x6, c2, c);
}
__device__ __forceinline__ float fneg_if(float v, bool neg) {
    return __uint_as_float(__float_as_uint(v) ^ (neg ? 0x80000000u : 0u));
}
__device__ __forceinline__ void gsc_sincosf2(float y, float* sp, float* cp) {
    double x = (double)y;
    unsigned at = gsc_abstop12(y);
    if (at < 0x3f4u) {
        if (at < 0x398u) { *sp = y; *cp = 1.0f; return; }
        double x2 = x * x;
        *sp = (float)gsc_sinpoly(x, x2);
        *cp = (float)gsc_cospoly(x2);
        return;
    }
    double r  = x * GSC_HPI_INV;
    double rd = rint(r);
    int    n  = (int)rd;
    x = fma(-rd, GSC_HPI, x);
    double x2 = x * x;
    float sv = (float)gsc_sinpoly(x, x2);
    float cv = (float)gsc_cospoly(x2);
    bool odd  = (n & 1) != 0;
    bool flip = (n & 2) != 0;
    if (!odd) { *sp = fneg_if(sv, flip); *cp = fneg_if(cv, flip); }
    else      { *sp = fneg_if(cv, flip); *cp = fneg_if(sv, !flip); }
}

// ---------------------------------------------------------------------------
// Probe: int64 vs int32 idx_kj
// ---------------------------------------------------------------------------
__global__ void probe_idx_kernel(const int* __restrict__ idx32, int n_check) {
    __shared__ int any_nz;
    if (threadIdx.x == 0) any_nz = 0;
    __syncthreads();
    for (int i = threadIdx.x; i < n_check; i += blockDim.x) {
        if (idx32[2 * i + 1] != 0) any_nz = 1;
    }
    __syncthreads();
    if (threadIdx.x == 0) g_idx_is64 = (any_nz == 0) ? 1 : 0;
}

// ---------------------------------------------------------------------------
// Counting sort of edges by dist (256 bins) -> g_perm + g_inv
// ---------------------------------------------------------------------------
__global__ void zero_hist_kernel() {
    int t = threadIdx.x;
    if (t < 256) g_hist[t] = 0u;
}
__device__ __forceinline__ int dist_bin(float d) {
    int b = (int)((d - 0.1f) * (256.0f / 4.9f));
    return min(255, max(0, b));
}
__global__ void hist_kernel(const float* __restrict__ dist, int E) {
    __shared__ unsigned h[256];
    h[threadIdx.x] = 0u;
    __syncthreads();
    for (int i = blockIdx.x * blockDim.x + threadIdx.x; i < E;
         i += gridDim.x * blockDim.x)
        atomicAdd(&h[dist_bin(dist[i])], 1u);
    __syncthreads();
    if (h[threadIdx.x]) atomicAdd(&g_hist[threadIdx.x], h[threadIdx.x]);
}
__global__ void scan_kernel() {
    __shared__ unsigned tmp[256];
    int t = threadIdx.x;
    unsigned own = g_hist[t];
    tmp[t] = own;
    __syncthreads();
    for (int off = 1; off < 256; off <<= 1) {
        unsigned v = tmp[t];
        __syncthreads();
        if (t >= off) v += tmp[t - off];
        __syncthreads();
        tmp[t] = v;
        __syncthreads();
    }
    g_off[t] = tmp[t] - own;
}
__global__ void scatter_kernel(const float* __restrict__ dist, int E) {
    int i = blockIdx.x * blockDim.x + threadIdx.x;
    if (i >= E) return;
    unsigned pos = atomicAdd(&g_off[dist_bin(dist[i])], 1u);
    g_perm[pos] = i;
    g_inv[i] = (int)pos;
}

// ---------------------------------------------------------------------------
// K1: per-edge rbf, writes row at SORTED position i (coalesced via shared
// staging). Three precision tiers, warp-coherent via dist sort.
// ---------------------------------------------------------------------------
#define K1_STRIDE 50   // words per staged row (even, gcd(50,32)=2 -> <=2-way)
__global__ void __launch_bounds__(128) rbf_kernel(
    const float* __restrict__ dist,
    const float* __restrict__ zeros_lk,
    const float* __restrict__ norm_lk,
    int E)
{
    __shared__ float s_z [NSPH * NRAD];
    __shared__ float s_n [NSPH * NRAD];
    __shared__ float s_zi[NSPH * NRAD];
    __shared__ float s_stage[4][32 * K1_STRIDE];   // 4 warps * 6400B = 25.6KB
    if (threadIdx.x < NSPH * NRAD) {
        float z = zeros_lk[threadIdx.x];
        s_z [threadIdx.x] = z;
        s_n [threadIdx.x] = norm_lk[threadIdx.x];
        s_zi[threadIdx.x] = __fdiv_rn(1.0f, z);
    }
    __syncthreads();

    int warp = threadIdx.x >> 5;
    int lane = threadIdx.x & 31;
    int i = blockIdx.x * 128 + threadIdx.x;
    bool valid = (i < E);

    float* st = &s_stage[warp][lane * K1_STRIDE];

    if (valid) {
        int e = g_perm[i];
        float d = dist[e];
        float x = __fmul_rn(d, 0.2f);

        float x2  = __fmul_rn(x, x);
        float x4  = __fmul_rn(x2, x2);
        float xp0 = __fmul_rn(x4, x);

        float inv_x = __fdiv_rn(1.0f, x);
        float t2 = __fmul_rn(-28.0f, xp0);
        float t3 = __fmul_rn(__fmul_rn(48.0f, xp0), x);
        float t4 = __fmul_rn(__fmul_rn(__fmul_rn(-21.0f, xp0), x), x);
        float env = __fadd_rn(__fadd_rn(__fadd_rn(inv_x, t2), t3), t4);

        // l = 0: MUFU everywhere
        #pragma unroll
        for (int r = 0; r < NRAD; ++r) {
            float arg = __fmul_rn(x, s_z[r]);
            float inv = inv_x * s_zi[r];
            float j = __sinf(arg) * inv;
            st[r] = __fmul_rn(env, __fmul_rn(s_n[r], j));
        }
        // l = 1: accurate below th2, MUFU above
        {
            float th2 = c_th2[1];
            #pragma unroll
            for (int r = 0; r < NRAD; ++r) {
                float arg = __fmul_rn(x, s_z[NRAD + r]);
                float inv = inv_x * s_zi[NRAD + r];
                float s, c;
                if (arg < th2) sincosf(arg, &s, &c);
                else           __sincosf(arg, &s, &c);
                float j0 = s * inv;
                float j  = (j0 - c) * inv;
                st[NRAD + r] = __fmul_rn(env, __fmul_rn(s_n[NRAD + r], j));
            }
        }
        // l = 2..6: three tiers
        #pragma unroll 1
        for (int l = 2; l < NSPH; ++l) {
            float th  = c_th[l];
            float th2 = c_th2[l];
            #pragma unroll 1
            for (int r = 0; r < NRAD; ++r) {
                float arg = __fmul_rn(x, s_z[l * NRAD + r]);
                float j;
                if (arg < th) {
                    // exact reference path (bit-identical to round 9)
                    float s, c;
                    gsc_sincosf2(arg, &s, &c);
                    float j0 = __fdiv_rn(s, arg);
                    float jc = __fsub_rn(__fdiv_rn(s, __fmul_rn(arg, arg)),
                                         __fdiv_rn(c, arg));
                    float jm = j0;
                    for (int ii = 2; ii <= l; ++ii) {
                        float coef = __fdiv_rn((float)(2 * ii - 1), arg);
                        float jn = __fsub_rn(__fmul_rn(coef, jc), jm);
                        jm = jc; jc = jn;
                    }
                    j = jc;
                } else {
                    float inv = inv_x * s_zi[l * NRAD + r];
                    float s, c;
                    if (arg < th2) sincosf(arg, &s, &c);
                    else           __sincosf(arg, &s, &c);
                    float j0 = s * inv;
                    float jc = (j0 - c) * inv;
                    float jm = j0;
                    #pragma unroll
                    for (int ii = 2; ii <= 6; ++ii) {
                        if (ii > l) break;
                        float jn = fmaf((float)(2 * ii - 1) * inv, jc, -jm);
                        jm = jc; jc = jn;
                    }
                    j = jc;
                }
                st[l * NRAD + r] = __fmul_rn(env, __fmul_rn(s_n[l * NRAD + r], j));
            }
        }
        // pad
        st[42] = 0.f; st[43] = 0.f; st[44] = 0.f; st[45] = 0.f;
        st[46] = 0.f; st[47] = 0.f;
    }
    __syncwarp();

    // coalesced writeout: this warp's 32 rows = contiguous 32*48 floats
    int warp_row0 = blockIdx.x * 128 + warp * 32;
    int nrows = E - warp_row0;
    if (nrows <= 0) return;
    if (nrows > 32) nrows = 32;
    float* gbase = g_rbf + (size_t)warp_row0 * ROW;
    #pragma unroll
    for (int it = 0; it < 24; ++it) {         // 24*32 float2 = 32 rows * 24
        int k = it * 32 + lane;               // float2 index
        int rowl = k / 24;
        int col2 = k % 24;
        if (rowl < nrows) {
            float2 v = *reinterpret_cast<float2*>(
                &s_stage[warp][rowl * K1_STRIDE + col2 * 2]);
            *reinterpret_cast<float2*>(gbase + rowl * ROW + col2 * 2) = v;
        }
    }
}

// ---------------------------------------------------------------------------
// K2: per-triplet gather + Legendre * coef, coalesced stores via staging.
// ---------------------------------------------------------------------------
#define K2_STRIDE 46   // words per staged row (even, gcd(46,32)=2 -> <=2-way)
__global__ void __launch_bounds__(128) out_kernel(
    const float* __restrict__ angle,
    const int* __restrict__ idx32,
    float* __restrict__ out,
    int T)
{
    __shared__ float s_o[4][32 * K2_STRIDE];   // 4 * 5888B = 23.5KB

    int warp = threadIdx.x >> 5;
    int lane = threadIdx.x & 31;
    int t = blockIdx.x * 128 + threadIdx.x;
    float* st = &s_o[warp][lane * K2_STRIDE];

    if (t < T) {
        int e = g_idx_is64 ? idx32[2 * t] : idx32[t];
        int pos = g_inv[e];

        float ct = cosf(angle[t]);
        float P0 = 1.0f;
        float P1 = ct;
        float P2 = __fmul_rn(__fsub_rn(__fmul_rn(__fmul_rn(3.0f,  ct), P1), P0),                   0.5f);
        float P3 = __fmul_rn(__fsub_rn(__fmul_rn(__fmul_rn(5.0f,  ct), P2), __fmul_rn(2.0f, P1)), 0.33333334f);
        float P4 = __fmul_rn(__fsub_rn(__fmul_rn(__fmul_rn(7.0f,  ct), P3), __fmul_rn(3.0f, P2)), 0.25f);
        float P5 = __fmul_rn(__fsub_rn(__fmul_rn(__fmul_rn(9.0f,  ct), P4), __fmul_rn(4.0f, P3)), 0.2f);
        float P6 = __fmul_rn(__fsub_rn(__fmul_rn(__fmul_rn(11.0f, ct), P5), __fmul_rn(5.0f, P4)), 0.16666667f);

        float cbf[NSPH];
        cbf[0] = __fmul_rn(P0, c_coef[0]);
        cbf[1] = __fmul_rn(P1, c_coef[1]);
        cbf[2] = __fmul_rn(P2, c_coef[2]);
        cbf[3] = __fmul_rn(P3, c_coef[3]);
        cbf[4] = __fmul_rn(P4, c_coef[4]);
        cbf[5] = __fmul_rn(P5, c_coef[5]);
        cbf[6] = __fmul_rn(P6, c_coef[6]);

        const float4* src = reinterpret_cast<const float4*>(
            g_rbf + (size_t)pos * ROW);
        #pragma unroll
        for (int q = 0; q < 10; ++q) {
            float4 f = src[q];
            int k0 = 4 * q;
            st[k0 + 0] = __fmul_rn(f.x, cbf[(k0 + 0) / 6]);
            st[k0 + 1] = __fmul_rn(f.y, cbf[(k0 + 1) / 6]);
            st[k0 + 2] = __fmul_rn(f.z, cbf[(k0 + 2) / 6]);
            st[k0 + 3] = __fmul_rn(f.w, cbf[(k0 + 3) / 6]);
        }
        {   // last 2 of 42
            float2 f = *reinterpret_cast<const float2*>(
                g_rbf + (size_t)pos * ROW + 40);
            st[40] = __fmul_rn(f.x, cbf[6]);
            st[41] = __fmul_rn(f.y, cbf[6]);
        }
        st[42] = 0.f; st[43] = 0.f; st[44] = 0.f; st[45] = 0.f;
    }
    __syncwarp();

    // coalesced writeout: warp's 32 rows * 42 floats = contiguous 5376B
    int warp_t0 = blockIdx.x * 128 + warp * 32;
    int nrows = T - warp_t0;
    if (nrows <= 0) return;
    if (nrows > 32) nrows = 32;
    float* gbase = out + (size_t)warp_t0 * 42;
    #pragma unroll
    for (int it = 0; it < 21; ++it) {          // 21*32 float2 = 32 rows * 21
        int k = it * 32 + lane;
        int rowl = k / 21;
        int col2 = k % 21;
        if (rowl < nrows) {
            float2 v = *reinterpret_cast<float2*>(
                &s_o[warp][rowl * K2_STRIDE + col2 * 2]);
            *reinterpret_cast<float2*>(gbase + rowl * 42 + col2 * 2) = v;
        }
    }
}

// ---------------------------------------------------------------------------
// Launch
// ---------------------------------------------------------------------------
extern "C" void kernel_launch(void* const* d_in, const int* in_sizes, int n_in,
                              void* d_out, int out_size)
{
    const float* dist     = (const float*)d_in[0];
    const float* angle    = (const float*)d_in[1];
    const int*   idx32    = (const int*)  d_in[2];
    const float* zeros_lk = (const float*)d_in[3];
    const float* norm_lk  = (const float*)d_in[4];
    float* out = (float*)d_out;

    int E = in_sizes[0];
    int T = in_sizes[1];
    if (E > CAP_E) E = CAP_E;

    int n_check = 2048;
    if (2 * n_check > T) n_check = T / 2;
    probe_idx_kernel<<<1, 256>>>(idx32, n_check);

    zero_hist_kernel<<<1, 256>>>();
    hist_kernel<<<296, 256>>>(dist, E);
    scan_kernel<<<1, 256>>>();
    scatter_kernel<<<(E + 255) / 256, 256>>>(dist, E);

    rbf_kernel<<<(E + 127) / 128, 128>>>(dist, zeros_lk, norm_lk, E);
    out_kernel<<<(T + 127) / 128, 128>>>(angle, idx32, out, T);
}

// round 16
// speedup vs baseline: 7.1753x; 1.1812x over previous
#include <cuda_runtime.h>
#include <math.h>
#include <stdint.h>

// Problem constants
#define NSPH 7
#define NRAD 6
#define ROW  48          // padded rbf row (42 used), 192 bytes
#define CAP_E 1048576    // capacity for edges (E = 1,000,000)

// Scratch (static device arrays; no allocation)
__device__ float g_rbf[(size_t)CAP_E * ROW];   // indexed by SORTED position
__device__ int   g_perm[CAP_E];                // sorted pos -> edge (unused now)
__device__ int   g_inv [CAP_E];                // edge -> sorted pos
__device__ float g_dist_sorted[CAP_E];         // dist in sorted order
__device__ unsigned g_hist[256];
__device__ unsigned g_off[256];
__device__ unsigned g_hist_done;
__device__ int   g_idx_is64;

// sqrt((2l+1)/(4*pi)) in double, rounded to f32 (matches numpy cast)
__device__ __constant__ float c_coef[NSPH] = {
    (float)0.28209479177387814,
    (float)0.48860251190291992,
    (float)0.63078313050504009,
    (float)0.74635266518023078,
    (float)0.84628437532163443,
    (float)0.93560257962738882,
    (float)1.01710723628205748
};

// tiers: arg < th -> bit-exact DP; [th, th2) -> accurate sincosf; else MUFU
__device__ __constant__ float c_th [NSPH] = {0.0f, 0.0f, 0.45f, 0.85f, 1.30f, 1.75f, 2.20f};
__device__ __constant__ float c_th2[NSPH] = {0.0f, 0.50f, 1.25f, 1.70f, 2.20f, 2.75f, 3.30f};

// ===========================================================================
// glibc scalar sinf/cosf port (bit-exact vs reference, round 9 rel_err==0)
// ===========================================================================
#define GSC_HPI_INV 0x1.45F306DC9C883p-1
#define GSC_HPI     0x1.921FB54442D18p0
#define GSC_C0  (1.0)
#define GSC_C1  (-0x1.ffffffd0c621cp-2)
#define GSC_C2  ( 0x1.55553e1068f19p-5)
#define GSC_C3  (-0x1.6c087e89a359dp-10)
#define GSC_C4  ( 0x1.99343027bf8c3p-16)
#define GSC_S1  (-0x1.555545995a603p-3)
#define GSC_S2  ( 0x1.1107605230bc4p-7)
#define GSC_S3  (-0x1.994eb3774cf24p-13)

__device__ __forceinline__ unsigned gsc_abstop12(float y) {
    return (__float_as_uint(y) >> 20) & 0x7ffu;
}
__device__ __forceinline__ double gsc_sinpoly(double x, double x2) {
    double x3 = x * x2;
    double s1 = fma(x2, GSC_S3, GSC_S2);
    double x7 = x3 * x2;
    double s  = fma(x3, GSC_S1, x);
    return fma(x7, s1, s);
}
__device__ __forceinline__ double gsc_cospoly(double x2) {
    double x4 = x2 * x2;
    double c2 = fma(x2, GSC_C4, GSC_C3);
    double c1 = fma(x2, GSC_C1, GSC_C0);
    double x6 = x4 * x2;
    double c  = fma(x4, GSC_C2, c1);
    return fma(x6, c2, c);
}
__device__ __forceinline__ float fneg_if(float v, bool neg) {
    return __uint_as_float(__float_as_uint(v) ^ (neg ? 0x80000000u : 0u));
}
__device__ __forceinline__ void gsc_sincosf2(float y, float* sp, float* cp) {
    double x = (double)y;
    unsigned at = gsc_abstop12(y);
    if (at < 0x3f4u) {
        if (at < 0x398u) { *sp = y; *cp = 1.0f; return; }
        double x2 = x * x;
        *sp = (float)gsc_sinpoly(x, x2);
        *cp = (float)gsc_cospoly(x2);
        return;
    }
    double r  = x * GSC_HPI_INV;
    double rd = rint(r);
    int    n  = (int)rd;
    x = fma(-rd, GSC_HPI, x);
    double x2 = x * x;
    float sv = (float)gsc_sinpoly(x, x2);
    float cv = (float)gsc_cospoly(x2);
    bool odd  = (n & 1) != 0;
    bool flip = (n & 2) != 0;
    if (!odd) { *sp = fneg_if(sv, flip); *cp = fneg_if(cv, flip); }
    else      { *sp = fneg_if(cv, flip); *cp = fneg_if(sv, !flip); }
}

// ---------------------------------------------------------------------------
// Launch 0: probe idx dtype + zero hist state
// ---------------------------------------------------------------------------
__global__ void probe_zero_kernel(const int* __restrict__ idx32, int n_check) {
    __shared__ int any_nz;
    int t = threadIdx.x;
    if (t == 0) any_nz = 0;
    g_hist[t] = 0u;
    if (t == 0) g_hist_done = 0u;
    __syncthreads();
    for (int i = t; i < n_check; i += blockDim.x) {
        if (idx32[2 * i + 1] != 0) any_nz = 1;
    }
    __syncthreads();
    if (t == 0) g_idx_is64 = (any_nz == 0) ? 1 : 0;
}

// ---------------------------------------------------------------------------
// Launch 1: histogram + (last block) exclusive scan
// ---------------------------------------------------------------------------
__device__ __forceinline__ int dist_bin(float d) {
    int b = (int)((d - 0.1f) * (256.0f / 4.9f));
    return min(255, max(0, b));
}
__global__ void hist_scan_kernel(const float* __restrict__ dist, int E) {
    __shared__ unsigned h[256];
    __shared__ bool last;
    int t = threadIdx.x;
    h[t] = 0u;
    __syncthreads();
    for (int i = blockIdx.x * blockDim.x + t; i < E; i += gridDim.x * blockDim.x)
        atomicAdd(&h[dist_bin(dist[i])], 1u);
    __syncthreads();
    if (h[t]) atomicAdd(&g_hist[t], h[t]);
    __threadfence();
    __syncthreads();
    if (t == 0) {
        unsigned prev = atomicAdd(&g_hist_done, 1u);
        last = (prev == gridDim.x - 1);
    }
    __syncthreads();
    if (last) {
        __shared__ unsigned tmp[256];
        unsigned own = g_hist[t];
        tmp[t] = own;
        __syncthreads();
        for (int off = 1; off < 256; off <<= 1) {
            unsigned v = tmp[t];
            __syncthreads();
            if (t >= off) v += tmp[t - off];
            __syncthreads();
            tmp[t] = v;
            __syncthreads();
        }
        g_off[t] = tmp[t] - own;
    }
}

// ---------------------------------------------------------------------------
// Launch 2: scatter -> g_inv, g_dist_sorted
// ---------------------------------------------------------------------------
__global__ void scatter_kernel(const float* __restrict__ dist, int E) {
    int i = blockIdx.x * blockDim.x + threadIdx.x;
    if (i >= E) return;
    float d = dist[i];
    unsigned pos = atomicAdd(&g_off[dist_bin(d)], 1u);
    g_inv[i] = (int)pos;
    g_dist_sorted[pos] = d;
}

// ---------------------------------------------------------------------------
// Launch 3: K1 per-edge rbf (PROFILING TARGET). Writes row at sorted
// position i, coalesced via shared staging. Three precision tiers.
// ---------------------------------------------------------------------------
#define K1_STRIDE 50
__global__ void __launch_bounds__(128) rbf_kernel(
    const float* __restrict__ zeros_lk,
    const float* __restrict__ norm_lk,
    int E)
{
    __shared__ float s_z [NSPH * NRAD];
    __shared__ float s_n [NSPH * NRAD];
    __shared__ float s_zi[NSPH * NRAD];
    __shared__ float s_stage[4][32 * K1_STRIDE];
    if (threadIdx.x < NSPH * NRAD) {
        float z = zeros_lk[threadIdx.x];
        s_z [threadIdx.x] = z;
        s_n [threadIdx.x] = norm_lk[threadIdx.x];
        s_zi[threadIdx.x] = __fdiv_rn(1.0f, z);
    }
    __syncthreads();

    int warp = threadIdx.x >> 5;
    int lane = threadIdx.x & 31;
    int i = blockIdx.x * 128 + threadIdx.x;
    float* st = &s_stage[warp][lane * K1_STRIDE];

    if (i < E) {
        float d = g_dist_sorted[i];            // coalesced
        float x = __fmul_rn(d, 0.2f);

        float x2  = __fmul_rn(x, x);
        float x4  = __fmul_rn(x2, x2);
        float xp0 = __fmul_rn(x4, x);

        float inv_x = __fdiv_rn(1.0f, x);
        float t2 = __fmul_rn(-28.0f, xp0);
        float t3 = __fmul_rn(__fmul_rn(48.0f, xp0), x);
        float t4 = __fmul_rn(__fmul_rn(__fmul_rn(-21.0f, xp0), x), x);
        float env = __fadd_rn(__fadd_rn(__fadd_rn(inv_x, t2), t3), t4);

        // l = 0: MUFU everywhere
        #pragma unroll
        for (int r = 0; r < NRAD; ++r) {
            float arg = __fmul_rn(x, s_z[r]);
            float inv = inv_x * s_zi[r];
            float j = __sinf(arg) * inv;
            st[r] = __fmul_rn(env, __fmul_rn(s_n[r], j));
        }
        // l = 1: accurate below th2, MUFU above
        {
            float th2 = c_th2[1];
            #pragma unroll
            for (int r = 0; r < NRAD; ++r) {
                float arg = __fmul_rn(x, s_z[NRAD + r]);
                float inv = inv_x * s_zi[NRAD + r];
                float s, c;
                if (arg < th2) sincosf(arg, &s, &c);
                else           __sincosf(arg, &s, &c);
                float j0 = s * inv;
                float j  = (j0 - c) * inv;
                st[NRAD + r] = __fmul_rn(env, __fmul_rn(s_n[NRAD + r], j));
            }
        }
        // l = 2..6: three tiers
        #pragma unroll 1
        for (int l = 2; l < NSPH; ++l) {
            float th  = c_th[l];
            float th2 = c_th2[l];
            #pragma unroll 1
            for (int r = 0; r < NRAD; ++r) {
                float arg = __fmul_rn(x, s_z[l * NRAD + r]);
                float j;
                if (arg < th) {
                    // exact reference path (bit-identical to round 9)
                    float s, c;
                    gsc_sincosf2(arg, &s, &c);
                    float j0 = __fdiv_rn(s, arg);
                    float jc = __fsub_rn(__fdiv_rn(s, __fmul_rn(arg, arg)),
                                         __fdiv_rn(c, arg));
                    float jm = j0;
                    for (int ii = 2; ii <= l; ++ii) {
                        float coef = __fdiv_rn((float)(2 * ii - 1), arg);
                        float jn = __fsub_rn(__fmul_rn(coef, jc), jm);
                        jm = jc; jc = jn;
                    }
                    j = jc;
                } else {
                    float inv = inv_x * s_zi[l * NRAD + r];
                    float s, c;
                    if (arg < th2) sincosf(arg, &s, &c);
                    else           __sincosf(arg, &s, &c);
                    float j0 = s * inv;
                    float jc = (j0 - c) * inv;
                    float jm = j0;
                    #pragma unroll
                    for (int ii = 2; ii <= 6; ++ii) {
                        if (ii > l) break;
                        float jn = fmaf((float)(2 * ii - 1) * inv, jc, -jm);
                        jm = jc; jc = jn;
                    }
                    j = jc;
                }
                st[l * NRAD + r] = __fmul_rn(env, __fmul_rn(s_n[l * NRAD + r], j));
            }
        }
        st[42] = 0.f; st[43] = 0.f; st[44] = 0.f; st[45] = 0.f;
        st[46] = 0.f; st[47] = 0.f;
    }
    __syncwarp();

    int warp_row0 = blockIdx.x * 128 + warp * 32;
    int nrows = E - warp_row0;
    if (nrows <= 0) return;
    if (nrows > 32) nrows = 32;
    float* gbase = g_rbf + (size_t)warp_row0 * ROW;
    #pragma unroll
    for (int it = 0; it < 24; ++it) {
        int k = it * 32 + lane;
        int rowl = k / 24;
        int col2 = k % 24;
        if (rowl < nrows) {
            float2 v = *reinterpret_cast<float2*>(
                &s_stage[warp][rowl * K1_STRIDE + col2 * 2]);
            *reinterpret_cast<float2*>(gbase + rowl * ROW + col2 * 2) = v;
        }
    }
}

// ---------------------------------------------------------------------------
// Launch 4: K2 per-triplet gather + Legendre * coef, coalesced stores.
// ---------------------------------------------------------------------------
#define K2_STRIDE 46
__global__ void __launch_bounds__(256) out_kernel(
    const float* __restrict__ angle,
    const int* __restrict__ idx32,
    float* __restrict__ out,
    int T)
{
    __shared__ float s_o[8][32 * K2_STRIDE];   // 8 warps * 5888B = 47KB

    int warp = threadIdx.x >> 5;
    int lane = threadIdx.x & 31;
    int t = blockIdx.x * 256 + threadIdx.x;
    float* st = &s_o[warp][lane * K2_STRIDE];

    if (t < T) {
        int e = g_idx_is64 ? idx32[2 * t] : idx32[t];
        int pos = g_inv[e];

        float ct = cosf(angle[t]);
        float P0 = 1.0f;
        float P1 = ct;
        float P2 = __fmul_rn(__fsub_rn(__fmul_rn(__fmul_rn(3.0f,  ct), P1), P0),                   0.5f);
        float P3 = __fmul_rn(__fsub_rn(__fmul_rn(__fmul_rn(5.0f,  ct), P2), __fmul_rn(2.0f, P1)), 0.33333334f);
        float P4 = __fmul_rn(__fsub_rn(__fmul_rn(__fmul_rn(7.0f,  ct), P3), __fmul_rn(3.0f, P2)), 0.25f);
        float P5 = __fmul_rn(__fsub_rn(__fmul_rn(__fmul_rn(9.0f,  ct), P4), __fmul_rn(4.0f, P3)), 0.2f);
        float P6 = __fmul_rn(__fsub_rn(__fmul_rn(__fmul_rn(11.0f, ct), P5), __fmul_rn(5.0f, P4)), 0.16666667f);

        float cbf[NSPH];
        cbf[0] = __fmul_rn(P0, c_coef[0]);
        cbf[1] = __fmul_rn(P1, c_coef[1]);
        cbf[2] = __fmul_rn(P2, c_coef[2]);
        cbf[3] = __fmul_rn(P3, c_coef[3]);
        cbf[4] = __fmul_rn(P4, c_coef[4]);
        cbf[5] = __fmul_rn(P5, c_coef[5]);
        cbf[6] = __fmul_rn(P6, c_coef[6]);

        const float4* src = reinterpret_cast<const float4*>(
            g_rbf + (size_t)pos * ROW);
        #pragma unroll
        for (int q = 0; q < 10; ++q) {
            float4 f = src[q];
            int k0 = 4 * q;
            st[k0 + 0] = __fmul_rn(f.x, cbf[(k0 + 0) / 6]);
            st[k0 + 1] = __fmul_rn(f.y, cbf[(k0 + 1) / 6]);
            st[k0 + 2] = __fmul_rn(f.z, cbf[(k0 + 2) / 6]);
            st[k0 + 3] = __fmul_rn(f.w, cbf[(k0 + 3) / 6]);
        }
        {
            float2 f = *reinterpret_cast<const float2*>(
                g_rbf + (size_t)pos * ROW + 40);
            st[40] = __fmul_rn(f.x, cbf[6]);
            st[41] = __fmul_rn(f.y, cbf[6]);
        }
        st[42] = 0.f; st[43] = 0.f; st[44] = 0.f; st[45] = 0.f;
    }
    __syncwarp();

    int warp_t0 = blockIdx.x * 256 + warp * 32;
    int nrows = T - warp_t0;
    if (nrows <= 0) return;
    if (nrows > 32) nrows = 32;
    float* gbase = out + (size_t)warp_t0 * 42;
    #pragma unroll
    for (int it = 0; it < 21; ++it) {
        int k = it * 32 + lane;
        int rowl = k / 21;
        int col2 = k % 21;
        if (rowl < nrows) {
            float2 v = *reinterpret_cast<float2*>(
                &s_o[warp][rowl * K2_STRIDE + col2 * 2]);
            *reinterpret_cast<float2*>(gbase + rowl * 42 + col2 * 2) = v;
        }
    }
}

// ---------------------------------------------------------------------------
// Launch
// ---------------------------------------------------------------------------
extern "C" void kernel_launch(void* const* d_in, const int* in_sizes, int n_in,
                              void* d_out, int out_size)
{
    const float* dist     = (const float*)d_in[0];
    const float* angle    = (const float*)d_in[1];
    const int*   idx32    = (const int*)  d_in[2];
    const float* zeros_lk = (const float*)d_in[3];
    const float* norm_lk  = (const float*)d_in[4];
    float* out = (float*)d_out;

    int E = in_sizes[0];
    int T = in_sizes[1];
    if (E > CAP_E) E = CAP_E;

    int n_check = 2048;
    if (2 * n_check > T) n_check = T / 2;

    probe_zero_kernel<<<1, 256>>>(idx32, n_check);              // launch 0
    hist_scan_kernel<<<296, 256>>>(dist, E);                    // launch 1
    scatter_kernel<<<(E + 255) / 256, 256>>>(dist, E);          // launch 2
    rbf_kernel<<<(E + 127) / 128, 128>>>(zeros_lk, norm_lk, E); // launch 3
    out_kernel<<<(T + 255) / 256, 256>>>(angle, idx32, out, T); // launch 4
}